// round 9
// baseline (speedup 1.0000x reference)
#include <cuda.h>
#include <cuda_runtime.h>
#include <cuda_bf16.h>
#include <math.h>
#include <stdint.h>

#define B_    64
#define L_    1024
#define N_    64
#define INSZ  128
#define MEM   1024
#define DEC   3

#define NCTA  128
#define NT    256
#define JB    8

// ---------------- scratch ----------------------------------------------------
__device__ float g_inter[(size_t)L_ * B_ * INSZ];
__device__ float g_proj [(size_t)L_ * 3 * MEM * B_];          // [l][col][b]
__device__ __nv_bfloat16 g_hsplit[128 * MEM];                 // rows 0-63 hi, 64-127 lo
__device__ float g_mem  [(size_t)L_ * MEM * B_];              // [l][j][b]
__device__ unsigned int g_bar_count;
__device__ unsigned int g_bar_gen;

// ---------------- PTX helpers ------------------------------------------------
__device__ __forceinline__ uint32_t smem_u32(const void* p) {
    uint32_t a;
    asm("{ .reg .u64 t; cvta.to.shared.u64 t, %1; cvt.u32.u64 %0, t; }" : "=r"(a) : "l"(p));
    return a;
}
#define SWZ(o) ((o) ^ (((o) >> 3) & 0x70))

#define MBAR_INIT(a, c) asm volatile("mbarrier.init.shared.b64 [%0], %1;" :: "r"((uint32_t)(a)), "r"((uint32_t)(c)) : "memory")
#define MBAR_EXPECT_TX(a, n) asm volatile("mbarrier.arrive.expect_tx.shared.b64 _, [%0], %1;" :: "r"((uint32_t)(a)), "r"((uint32_t)(n)) : "memory")
#define MBAR_ARRIVE(a) asm volatile("mbarrier.arrive.shared.b64 _, [%0];" :: "r"((uint32_t)(a)) : "memory")

#define MBAR_WAIT(a, par) do { \
    uint32_t _m = (uint32_t)(a); uint32_t _p = (uint32_t)(par); uint32_t _d; \
    asm volatile("{\n\t.reg .pred p;\n\t" \
        "mbarrier.try_wait.parity.acquire.cta.shared::cta.b64 p, [%1], %2;\n\t" \
        "selp.b32 %0, 1, 0, p;\n\t}" : "=r"(_d) : "r"(_m), "r"(_p) : "memory"); \
    if (!_d) { \
        asm volatile("{\n\t.reg .pred P1;\n\tWL_%=:\n\t" \
            "mbarrier.try_wait.parity.acquire.cta.shared::cta.b64 P1, [%0], %1, 0x989680;\n\t" \
            "@P1 bra.uni WD_%=;\n\tbra.uni WL_%=;\n\tWD_%=:\n\t}" \
            :: "r"(_m), "r"(_p) : "memory"); \
    } } while (0)

#define TMA_LD(dst, tm, cx, cy, cz, mbar) \
    asm volatile("cp.async.bulk.tensor.3d.shared::cta.global.tile.mbarrier::complete_tx::bytes " \
        "[%0], [%1, {%2, %3, %4}], [%5];" \
        :: "r"((uint32_t)(dst)), "l"(tm), "r"((int32_t)(cx)), "r"((int32_t)(cy)), "r"((int32_t)(cz)), \
           "r"((uint32_t)(mbar)) : "memory")

#define FENCE_ASYNC_ALL() asm volatile("fence.proxy.async;" ::: "memory")
#define BAR_ARRIVE(id, cnt) asm volatile("bar.arrive %0, %1;" :: "r"(id), "r"(cnt) : "memory")
#define BAR_SYNC(id, cnt)   asm volatile("bar.sync %0, %1;"   :: "r"(id), "r"(cnt) : "memory")

__device__ __forceinline__ void ldmatrix4(uint32_t& a0, uint32_t& a1, uint32_t& a2, uint32_t& a3,
                                          uint32_t addr) {
    asm volatile("ldmatrix.sync.aligned.m8n8.x4.shared.b16 {%0,%1,%2,%3}, [%4];"
        : "=r"(a0), "=r"(a1), "=r"(a2), "=r"(a3) : "r"(addr));
}
__device__ __forceinline__ void mma16816(float* d, uint32_t a0, uint32_t a1, uint32_t a2, uint32_t a3,
                                         uint32_t b0, uint32_t b1) {
    asm volatile("mma.sync.aligned.m16n8k16.row.col.f32.bf16.bf16.f32 "
        "{%0,%1,%2,%3}, {%4,%5,%6,%7}, {%8,%9}, {%0,%1,%2,%3};"
        : "+f"(d[0]), "+f"(d[1]), "+f"(d[2]), "+f"(d[3])
        : "r"(a0), "r"(a1), "r"(a2), "r"(a3), "r"(b0), "r"(b1));
}

__device__ __forceinline__ float tanh_acc(float x) {
    float ax = fabsf(x);
    float e  = __expf(-2.0f * ax);
    float t  = (1.0f - e) / (1.0f + e);
    return copysignf(t, x);
}
__device__ __forceinline__ float sigmoid_acc(float z) {
    return 1.0f / (1.0f + __expf(-z));
}
__device__ __forceinline__ uint32_t packbf(float x, float y, bool lo) {
    __nv_bfloat16 xh = __float2bfloat16(x), yh = __float2bfloat16(y);
    if (lo) {
        xh = __float2bfloat16(x - __bfloat162float(xh));
        yh = __float2bfloat16(y - __bfloat162float(yh));
    }
    return ((uint32_t)__bfloat16_as_ushort(yh) << 16) | (uint32_t)__bfloat16_as_ushort(xh);
}

__global__ void reset_kernel() { g_bar_count = 0u; g_bar_gen = 0u; }

// ---------------- K1a: sense ---------------------------------------------------
__global__ void sense_kernel(const float* __restrict__ x,
                             const float* __restrict__ Ws,
                             const float* __restrict__ bs) {
    __shared__ float xs[N_];
    int bl = blockIdx.x;
    int b  = bl >> 10;
    int l  = bl & (L_ - 1);
    int t  = threadIdx.x;
    if (t < N_) xs[t] = x[(size_t)bl * N_ + t];
    __syncthreads();
    float acc = bs[t];
#pragma unroll 16
    for (int n = 0; n < N_; n++) acc += xs[n] * Ws[n * INSZ + t];
    g_inter[((size_t)l * B_ + b) * INSZ + t] = acc;
}

// ---------------- K1b: proj -----------------------------------------------------
#define CB 128
__global__ void __launch_bounds__(256) proj_kernel(const float* __restrict__ Wim) {
    extern __shared__ float sm[];
    float* As = sm;
    float* Bs = sm + INSZ * B_;
    int l  = blockIdx.x;
    int cb = blockIdx.y;
    int t  = threadIdx.x;

    for (int idx = t; idx < B_ * INSZ; idx += 256) {
        int b = idx >> 7, k = idx & 127;
        As[k * B_ + b] = g_inter[((size_t)l * B_ + b) * INSZ + k];
    }
    for (int idx = t; idx < INSZ * CB; idx += 256) {
        int k = idx >> 7, cc = idx & 127;
        Bs[k * CB + cc] = Wim[(size_t)k * (3 * MEM) + cb * CB + cc];
    }
    __syncthreads();

    int cg = t >> 3;
    int bg = t & 7;
    float acc[4][8];
#pragma unroll
    for (int i = 0; i < 4; i++)
#pragma unroll
        for (int j = 0; j < 8; j++) acc[i][j] = 0.0f;

    for (int k = 0; k < INSZ; k++) {
        float4 bv  = *(const float4*)&Bs[k * CB + cg * 4];
        float4 a0  = *(const float4*)&As[k * B_ + bg * 8];
        float4 a1  = *(const float4*)&As[k * B_ + bg * 8 + 4];
        float bb[4] = {bv.x, bv.y, bv.z, bv.w};
        float aa[8] = {a0.x, a0.y, a0.z, a0.w, a1.x, a1.y, a1.z, a1.w};
#pragma unroll
        for (int i = 0; i < 4; i++)
#pragma unroll
            for (int j = 0; j < 8; j++) acc[i][j] += bb[i] * aa[j];
    }

    size_t base = (size_t)l * (3 * MEM) * B_ + (size_t)(cb * CB) * B_;
#pragma unroll
    for (int i = 0; i < 4; i++) {
        size_t rb = base + (size_t)(cg * 4 + i) * B_ + bg * 8;
        *(float4*)&g_proj[rb]     = make_float4(acc[i][0], acc[i][1], acc[i][2], acc[i][3]);
        *(float4*)&g_proj[rb + 4] = make_float4(acc[i][4], acc[i][5], acc[i][6], acc[i][7]);
    }
}

// ---------------- grid barrier --------------------------------------------------
__device__ __forceinline__ void grid_barrier(unsigned int target) {
    __syncthreads();
    if (threadIdx.x == 0) {
        __threadfence();
        unsigned int tk = atomicAdd(&g_bar_count, 1u);
        if (tk == NCTA - 1) {
            atomicExch(&g_bar_count, 0u);
            __threadfence();
            atomicAdd(&g_bar_gen, 1u);
        } else {
            while (*(volatile unsigned int*)&g_bar_gen < target) { }
            __threadfence();
        }
    }
    __syncthreads();
}

// ---------------- K2: scan ------------------------------------------------------
// 8 warps: kg = wid>>1 (K quarter), mg = wid&1 (64 rows). W_hi in regs, W_lo smem.
// NO clusters (residency-safe). Per CTA, per step: A[128 x 1024]bf16 fetched as 4
// chunks of K=256 (64KB) into 2 slots via plain TMA. One FULL barrier per chunk
// (single completion per step, parity l&1). CONA/CONC (count 2, lane-0 arrives of
// the two kg0/kg1 warps) gate intra-step slot reuse; cross-step reuse is ordered
// by the grid barrier.
#define OFF_FULL   0      // FULL0..FULL3 at 0,8,16,24
#define OFF_CONA   32
#define OFF_CONC   40
#define OFF_WLO    1024
#define OFF_S0     33792
#define OFF_S1     99328
#define OFF_RED    164864
#define SMEM_SCAN  (164864 + 2 * 128 * 33 * 4)

__global__ void __launch_bounds__(NT, 1)
scan_tc(const float* __restrict__ Wmm, const __grid_constant__ CUtensorMap tmap) {
    extern __shared__ char smem[];
    uint32_t sb = smem_u32(smem);
    float* RED = (float*)(smem + OFF_RED);
    uint2* Wlo = (uint2*)(smem + OFF_WLO);
    int t = threadIdx.x, wid = t >> 5, lane = t & 31;
    int kg = wid >> 1, mg = wid & 1;
    int j0 = blockIdx.x * JB;

    if (t == 0) {
#pragma unroll
        for (int c = 0; c < 4; c++) MBAR_INIT(sb + OFF_FULL + c * 8, 1);
        MBAR_INIT(sb + OFF_CONA, 2);
        MBAR_INIT(sb + OFF_CONC, 2);
    }

    // W_hi fragments in registers (per-warp K quarter, n = a(8)|c(8))
    uint2 wf[16][2];
    {
        int jj = (lane >> 2) & 7;
#pragma unroll
        for (int kk = 0; kk < 16; kk++) {
            int k0 = kg * 256 + kk * 16 + (lane & 3) * 2;
            const float* wp = Wmm + (size_t)k0 * 2048;
#pragma unroll
            for (int np = 0; np < 2; np++) {
                int col = np * MEM + j0 + jj;
                wf[kk][np] = make_uint2(
                    packbf(wp[col], wp[2048 + col], false),
                    packbf(wp[8 * 2048 + col], wp[9 * 2048 + col], false));
            }
        }
    }
    // W_lo fragments in smem: [gk 64][np 2][lane 32]
    for (int idx = t; idx < 64 * 2 * 32; idx += NT) {
        int ln = idx & 31, np = (idx >> 5) & 1, gk = idx >> 6;
        int col = np * MEM + j0 + ((ln >> 2) & 7);
        int k0 = gk * 16 + (ln & 3) * 2;
        const float* wp = Wmm + (size_t)k0 * 2048;
        Wlo[idx] = make_uint2(
            packbf(wp[col], wp[2048 + col], true),
            packbf(wp[8 * 2048 + col], wp[9 * 2048 + col], true));
    }

    // init h
    float hreg[2] = {0.0f, 0.0f};
#pragma unroll
    for (int p = 0; p < 2; p++) {
        int idx = t + p * NT;
        int b = idx >> 3, jj = idx & 7, j = j0 + jj;
        g_hsplit[b * MEM + j]        = __float2bfloat16(0.0f);
        g_hsplit[(64 + b) * MEM + j] = __float2bfloat16(0.0f);
    }
    __syncthreads();

    unsigned int bar = 1;
    grid_barrier(bar);

    uint32_t myfull = sb + OFF_FULL + kg * 8;
    uint32_t myslot = sb + ((kg & 1) ? OFF_S1 : OFF_S0);
    int redbar = 5 + (kg & 1);

    for (int l = 0; l < L_; l++) {
        int par = l & 1;
        // proj terms
        float ia[2], ic[2], io[2];
        size_t pb = (size_t)l * 3072 * 64;
#pragma unroll
        for (int p = 0; p < 2; p++) {
            int idx = t + p * NT;
            int b = idx >> 3, j = j0 + (idx & 7);
            ia[p] = __ldg(&g_proj[pb + (size_t)j * 64 + b]);
            ic[p] = __ldg(&g_proj[pb + (size_t)(MEM + j) * 64 + b]);
            io[p] = __ldg(&g_proj[pb + (size_t)(2 * MEM + j) * 64 + b]);
        }

        // producer: chunks 0,1 (slot reuse across steps ordered by grid barrier)
        if (t == 0) {
            FENCE_ASYNC_ALL();
            MBAR_EXPECT_TX(sb + OFF_FULL + 0, 65536);
#pragma unroll
            for (int s = 0; s < 4; s++)
                TMA_LD(sb + OFF_S0 + s * 16384, &tmap,
                       0 * 256 + s * 64, 0, 0, sb + OFF_FULL + 0);
            MBAR_EXPECT_TX(sb + OFF_FULL + 8, 65536);
#pragma unroll
            for (int s = 0; s < 4; s++)
                TMA_LD(sb + OFF_S1 + s * 16384, &tmap,
                       1 * 256 + s * 64, 0, 0, sb + OFF_FULL + 8);
        }

        // consumer: wait my chunk (single completion per step -> parity l&1)
        MBAR_WAIT(myfull, par);

        float acc[4][4][4];
#pragma unroll
        for (int a = 0; a < 4; a++)
#pragma unroll
            for (int b2 = 0; b2 < 4; b2++)
#pragma unroll
                for (int c = 0; c < 4; c++) acc[a][b2][c] = 0.0f;

        int lbase = (lane & 15) * 128 + ((lane >> 4) << 4);
#pragma unroll
        for (int kk = 0; kk < 16; kk++) {
            uint2 blo0 = Wlo[((kg * 16 + kk) * 2 + 0) * 32 + lane];
            uint2 blo1 = Wlo[((kg * 16 + kk) * 2 + 1) * 32 + lane];
            uint32_t kbase = myslot + (uint32_t)((kk >> 2) * 16384);
            uint32_t loff  = (uint32_t)SWZ(lbase + (kk & 3) * 32);
#pragma unroll
            for (int mt = 0; mt < 4; mt++) {
                uint32_t addr = kbase + (uint32_t)((mg * 4 + mt) * 2048) + loff;
                uint32_t a0, a1, a2, a3;
                ldmatrix4(a0, a1, a2, a3, addr);
                mma16816(acc[mt][0], a0, a1, a2, a3, wf[kk][0].x, wf[kk][0].y);
                mma16816(acc[mt][1], a0, a1, a2, a3, wf[kk][1].x, wf[kk][1].y);
                mma16816(acc[mt][2], a0, a1, a2, a3, blo0.x, blo0.y);
                mma16816(acc[mt][3], a0, a1, a2, a3, blo1.x, blo1.y);
            }
        }

        // kg0/kg1: signal chunk consumed (one arrive per warp, count 2)
        if (kg == 0 && lane == 0) MBAR_ARRIVE(sb + OFF_CONA);
        if (kg == 1 && lane == 0) MBAR_ARRIVE(sb + OFF_CONC);

        // producer: chunks 2,3 (gated on intra-step consumption of S0/S1)
        if (t == 0) {
            MBAR_WAIT(sb + OFF_CONA, par);
            MBAR_EXPECT_TX(sb + OFF_FULL + 16, 65536);
#pragma unroll
            for (int s = 0; s < 4; s++)
                TMA_LD(sb + OFF_S0 + s * 16384, &tmap,
                       2 * 256 + s * 64, 0, 0, sb + OFF_FULL + 16);
            MBAR_WAIT(sb + OFF_CONC, par);
            MBAR_EXPECT_TX(sb + OFF_FULL + 24, 65536);
#pragma unroll
            for (int s = 0; s < 4; s++)
                TMA_LD(sb + OFF_S1 + s * 16384, &tmap,
                       3 * 256 + s * 64, 0, 0, sb + OFF_FULL + 24);
        }

        // RED: kg0/kg1 write, kg2/kg3 accumulate (ordered by named barrier)
        {
            float* rp = RED + (size_t)(kg & 1) * (128 * 33);
            int r0 = mg * 64 + (lane >> 2);
            int c0 = (lane & 3) * 2;
            if (kg < 2) {
#pragma unroll
                for (int mt = 0; mt < 4; mt++)
#pragma unroll
                    for (int np = 0; np < 4; np++) {
                        float* q = rp + (r0 + mt * 16) * 33 + np * 8 + c0;
                        q[0]          = acc[mt][np][0];
                        q[1]          = acc[mt][np][1];
                        q[8 * 33]     = acc[mt][np][2];
                        q[8 * 33 + 1] = acc[mt][np][3];
                    }
                BAR_ARRIVE(redbar, 128);
            } else {
                BAR_SYNC(redbar, 128);
#pragma unroll
                for (int mt = 0; mt < 4; mt++)
#pragma unroll
                    for (int np = 0; np < 4; np++) {
                        float* q = rp + (r0 + mt * 16) * 33 + np * 8 + c0;
                        q[0]          += acc[mt][np][0];
                        q[1]          += acc[mt][np][1];
                        q[8 * 33]     += acc[mt][np][2];
                        q[8 * 33 + 1] += acc[mt][np][3];
                    }
            }
        }
        __syncthreads();

        // combine + nBRC update
#pragma unroll
        for (int p = 0; p < 2; p++) {
            int idx = t + p * NT;
            int b = idx >> 3, jj = idx & 7, j = j0 + jj;
            float ma = 0.0f, mc = 0.0f;
#pragma unroll
            for (int q = 0; q < 2; q++) {
                const float* rq = RED + (size_t)q * (128 * 33);
                ma += rq[b * 33 + jj]          + rq[(64 + b) * 33 + jj]
                    + rq[b * 33 + 16 + jj]     + rq[(64 + b) * 33 + 16 + jj];
                mc += rq[b * 33 + 8 + jj]      + rq[(64 + b) * 33 + 8 + jj]
                    + rq[b * 33 + 24 + jj]     + rq[(64 + b) * 33 + 24 + jj];
            }
            float a  = 1.0f + tanh_acc(ia[p] + ma);
            float cg = sigmoid_acc(ic[p] + mc);
            float hn = cg * hreg[p] + (1.0f - cg) * tanh_acc(io[p] + a * hreg[p]);
            hreg[p] = hn;
            __nv_bfloat16 hh = __float2bfloat16(hn);
            __nv_bfloat16 hl = __float2bfloat16(hn - __bfloat162float(hh));
            g_hsplit[b * MEM + j]        = hh;
            g_hsplit[(64 + b) * MEM + j] = hl;
            g_mem[(size_t)l * (MEM * B_) + (size_t)j * B_ + b] = hn;
        }

        grid_barrier(++bar);
    }
}

// ---------------- K3: logits + softmax ------------------------------------------
__global__ void logits_kernel(const float* __restrict__ Wact,
                              const float* __restrict__ bact,
                              float* __restrict__ out) {
    __shared__ float Wa[MEM * DEC];
    int l = blockIdx.x;
    int b = threadIdx.x;
    for (int idx = b; idx < MEM * DEC; idx += B_) Wa[idx] = Wact[idx];
    __syncthreads();

    float a0 = bact[0], a1 = bact[1], a2 = bact[2];
    const float* mp = g_mem + (size_t)l * MEM * B_ + b;
#pragma unroll 8
    for (int k = 0; k < MEM; k++) {
        float v = mp[(size_t)k * B_];
        a0 += v * Wa[k * 3 + 0];
        a1 += v * Wa[k * 3 + 1];
        a2 += v * Wa[k * 3 + 2];
    }
    float m  = fmaxf(a0, fmaxf(a1, a2));
    float e0 = __expf(a0 - m), e1 = __expf(a1 - m), e2 = __expf(a2 - m);
    float inv = 1.0f / (e0 + e1 + e2);
    size_t ob = ((size_t)b * L_ + l) * DEC;
    out[ob + 0] = e0 * inv;
    out[ob + 1] = e1 * inv;
    out[ob + 2] = e2 * inv;
}

// ---------------- launch ----------------------------------------------------------
typedef CUresult (*PFN_tmapEncode)(
    CUtensorMap*, CUtensorMapDataType, cuuint32_t, void*,
    const cuuint64_t*, const cuuint64_t*, const cuuint32_t*, const cuuint32_t*,
    CUtensorMapInterleave, CUtensorMapSwizzle, CUtensorMapL2promotion,
    CUtensorMapFloatOOBfill);

extern "C" void kernel_launch(void* const* d_in, const int* in_sizes, int n_in,
                              void* d_out, int out_size) {
    (void)in_sizes; (void)n_in; (void)out_size;
    const float* x   = (const float*)d_in[0];
    const float* Ws  = (const float*)d_in[1];
    const float* bs  = (const float*)d_in[2];
    const float* Wim = (const float*)d_in[3];
    const float* Wmm = (const float*)d_in[4];
    const float* Wac = (const float*)d_in[5];
    const float* bac = (const float*)d_in[6];
    float* out = (float*)d_out;

    void* hs_ptr = nullptr;
    cudaGetSymbolAddress(&hs_ptr, g_hsplit);
    PFN_tmapEncode enc = nullptr;
    cudaDriverEntryPointQueryResult qr;
    cudaGetDriverEntryPoint("cuTensorMapEncodeTiled", (void**)&enc,
                            cudaEnableDefault, &qr);
    CUtensorMap tmap;
    {
        cuuint64_t dims[3]    = {MEM, 128, 1};
        cuuint64_t strides[2] = {MEM * 2, (cuuint64_t)MEM * 2 * 128};
        cuuint32_t box[3]     = {64, 128, 1};
        cuuint32_t es[3]      = {1, 1, 1};
        enc(&tmap, CU_TENSOR_MAP_DATA_TYPE_BFLOAT16, 3, hs_ptr,
            dims, strides, box, es,
            CU_TENSOR_MAP_INTERLEAVE_NONE, CU_TENSOR_MAP_SWIZZLE_128B,
            CU_TENSOR_MAP_L2_PROMOTION_L2_128B, CU_TENSOR_MAP_FLOAT_OOB_FILL_NONE);
    }

    cudaFuncSetAttribute(proj_kernel, cudaFuncAttributeMaxDynamicSharedMemorySize, 98304);
    cudaFuncSetAttribute(scan_tc,     cudaFuncAttributeMaxDynamicSharedMemorySize, SMEM_SCAN);

    reset_kernel<<<1, 1>>>();
    sense_kernel<<<B_ * L_, 128>>>(x, Ws, bs);
    proj_kernel<<<dim3(L_, 24), 256, 98304>>>(Wim);
    scan_tc<<<NCTA, NT, SMEM_SCAN>>>(Wmm, tmap);
    logits_kernel<<<L_, B_>>>(Wac, bac, out);
}

// round 10
// speedup vs baseline: 1.0094x; 1.0094x over previous
#include <cuda.h>
#include <cuda_runtime.h>
#include <cuda_bf16.h>
#include <math.h>
#include <stdint.h>

#define B_    64
#define L_    1024
#define N_    64
#define INSZ  128
#define MEM   1024
#define DEC   3

#define NCTA  128
#define NT    256
#define JB    8

// ---------------- scratch ----------------------------------------------------
__device__ float g_inter[(size_t)L_ * B_ * INSZ];
__device__ float g_proj [(size_t)L_ * 3 * MEM * B_];          // [l][col][b]
__device__ __nv_bfloat16 g_hsplit[128 * MEM];                 // rows 0-63 hi, 64-127 lo
__device__ float g_mem  [(size_t)L_ * MEM * B_];              // [l][j][b]
// two-level barrier state (monotonic; zeroed each launch by reset_kernel)
__device__ unsigned int g_cnt[8 * 64];                        // leaf counters, 256B apart
__device__ unsigned int g_fin;
__device__ unsigned int g_gen;

// ---------------- PTX helpers ------------------------------------------------
__device__ __forceinline__ uint32_t smem_u32(const void* p) {
    uint32_t a;
    asm("{ .reg .u64 t; cvta.to.shared.u64 t, %1; cvt.u32.u64 %0, t; }" : "=r"(a) : "l"(p));
    return a;
}
#define SWZ(o) ((o) ^ (((o) >> 3) & 0x70))

#define MBAR_INIT(a, c) asm volatile("mbarrier.init.shared.b64 [%0], %1;" :: "r"((uint32_t)(a)), "r"((uint32_t)(c)) : "memory")
#define MBAR_EXPECT_TX(a, n) asm volatile("mbarrier.arrive.expect_tx.shared.b64 _, [%0], %1;" :: "r"((uint32_t)(a)), "r"((uint32_t)(n)) : "memory")
#define MBAR_ARRIVE(a) asm volatile("mbarrier.arrive.shared.b64 _, [%0];" :: "r"((uint32_t)(a)) : "memory")

#define MBAR_WAIT(a, par) do { \
    uint32_t _m = (uint32_t)(a); uint32_t _p = (uint32_t)(par); uint32_t _d; \
    asm volatile("{\n\t.reg .pred p;\n\t" \
        "mbarrier.try_wait.parity.acquire.cta.shared::cta.b64 p, [%1], %2;\n\t" \
        "selp.b32 %0, 1, 0, p;\n\t}" : "=r"(_d) : "r"(_m), "r"(_p) : "memory"); \
    if (!_d) { \
        asm volatile("{\n\t.reg .pred P1;\n\tWL_%=:\n\t" \
            "mbarrier.try_wait.parity.acquire.cta.shared::cta.b64 P1, [%0], %1, 0x989680;\n\t" \
            "@P1 bra.uni WD_%=;\n\tbra.uni WL_%=;\n\tWD_%=:\n\t}" \
            :: "r"(_m), "r"(_p) : "memory"); \
    } } while (0)

#define TMA_LD(dst, tm, cx, cy, cz, mbar) \
    asm volatile("cp.async.bulk.tensor.3d.shared::cta.global.tile.mbarrier::complete_tx::bytes " \
        "[%0], [%1, {%2, %3, %4}], [%5];" \
        :: "r"((uint32_t)(dst)), "l"(tm), "r"((int32_t)(cx)), "r"((int32_t)(cy)), "r"((int32_t)(cz)), \
           "r"((uint32_t)(mbar)) : "memory")

#define FENCE_ASYNC_ALL() asm volatile("fence.proxy.async;" ::: "memory")
#define BAR_ARRIVE(id, cnt) asm volatile("bar.arrive %0, %1;" :: "r"(id), "r"(cnt) : "memory")
#define BAR_SYNC(id, cnt)   asm volatile("bar.sync %0, %1;"   :: "r"(id), "r"(cnt) : "memory")

__device__ __forceinline__ void ldmatrix4(uint32_t& a0, uint32_t& a1, uint32_t& a2, uint32_t& a3,
                                          uint32_t addr) {
    asm volatile("ldmatrix.sync.aligned.m8n8.x4.shared.b16 {%0,%1,%2,%3}, [%4];"
        : "=r"(a0), "=r"(a1), "=r"(a2), "=r"(a3) : "r"(addr));
}
__device__ __forceinline__ void mma16816(float* d, uint32_t a0, uint32_t a1, uint32_t a2, uint32_t a3,
                                         uint32_t b0, uint32_t b1) {
    asm volatile("mma.sync.aligned.m16n8k16.row.col.f32.bf16.bf16.f32 "
        "{%0,%1,%2,%3}, {%4,%5,%6,%7}, {%8,%9}, {%0,%1,%2,%3};"
        : "+f"(d[0]), "+f"(d[1]), "+f"(d[2]), "+f"(d[3])
        : "r"(a0), "r"(a1), "r"(a2), "r"(a3), "r"(b0), "r"(b1));
}

__device__ __forceinline__ float tanh_acc(float x) {
    float ax = fabsf(x);
    float e  = __expf(-2.0f * ax);
    float t  = (1.0f - e) / (1.0f + e);
    return copysignf(t, x);
}
__device__ __forceinline__ float sigmoid_acc(float z) {
    return 1.0f / (1.0f + __expf(-z));
}
__device__ __forceinline__ uint32_t packbf(float x, float y, bool lo) {
    __nv_bfloat16 xh = __float2bfloat16(x), yh = __float2bfloat16(y);
    if (lo) {
        xh = __float2bfloat16(x - __bfloat162float(xh));
        yh = __float2bfloat16(y - __bfloat162float(yh));
    }
    return ((uint32_t)__bfloat16_as_ushort(yh) << 16) | (uint32_t)__bfloat16_as_ushort(xh);
}

__global__ void reset_kernel() {
    int t = threadIdx.x;
    if (t < 512) g_cnt[t] = 0u;
    if (t == 0) { g_fin = 0u; g_gen = 0u; }
}

// ---------------- K1a: sense (8 tokens/block, W_s reused) -----------------------
__global__ void __launch_bounds__(128) sense_kernel(const float* __restrict__ x,
                                                    const float* __restrict__ Ws,
                                                    const float* __restrict__ bs) {
    __shared__ float xs[8][N_];
    int t = threadIdx.x;
    int bl0 = blockIdx.x * 8;
#pragma unroll
    for (int i = 0; i < 4; i++) {
        int idx = t + i * 128;
        xs[idx >> 6][idx & 63] = x[(size_t)bl0 * N_ + idx];
    }
    __syncthreads();
    float acc[8];
    float bias = bs[t];
#pragma unroll
    for (int i = 0; i < 8; i++) acc[i] = bias;
    for (int n = 0; n < N_; n++) {
        float w = Ws[n * INSZ + t];
#pragma unroll
        for (int i = 0; i < 8; i++) acc[i] += xs[i][n] * w;
    }
#pragma unroll
    for (int i = 0; i < 8; i++) {
        int bl = bl0 + i;
        int b = bl >> 10, l = bl & (L_ - 1);
        g_inter[((size_t)l * B_ + b) * INSZ + t] = acc[i];
    }
}

// ---------------- K1b: proj -----------------------------------------------------
#define CB 128
__global__ void __launch_bounds__(256) proj_kernel(const float* __restrict__ Wim) {
    extern __shared__ float sm[];
    float* As = sm;
    float* Bs = sm + INSZ * B_;
    int l  = blockIdx.x;
    int cb = blockIdx.y;
    int t  = threadIdx.x;

    for (int idx = t; idx < B_ * INSZ; idx += 256) {
        int b = idx >> 7, k = idx & 127;
        As[k * B_ + b] = g_inter[((size_t)l * B_ + b) * INSZ + k];
    }
    for (int idx = t; idx < INSZ * CB; idx += 256) {
        int k = idx >> 7, cc = idx & 127;
        Bs[k * CB + cc] = Wim[(size_t)k * (3 * MEM) + cb * CB + cc];
    }
    __syncthreads();

    int cg = t >> 3;
    int bg = t & 7;
    float acc[4][8];
#pragma unroll
    for (int i = 0; i < 4; i++)
#pragma unroll
        for (int j = 0; j < 8; j++) acc[i][j] = 0.0f;

    for (int k = 0; k < INSZ; k++) {
        float4 bv  = *(const float4*)&Bs[k * CB + cg * 4];
        float4 a0  = *(const float4*)&As[k * B_ + bg * 8];
        float4 a1  = *(const float4*)&As[k * B_ + bg * 8 + 4];
        float bb[4] = {bv.x, bv.y, bv.z, bv.w};
        float aa[8] = {a0.x, a0.y, a0.z, a0.w, a1.x, a1.y, a1.z, a1.w};
#pragma unroll
        for (int i = 0; i < 4; i++)
#pragma unroll
            for (int j = 0; j < 8; j++) acc[i][j] += bb[i] * aa[j];
    }

    size_t base = (size_t)l * (3 * MEM) * B_ + (size_t)(cb * CB) * B_;
#pragma unroll
    for (int i = 0; i < 4; i++) {
        size_t rb = base + (size_t)(cg * 4 + i) * B_ + bg * 8;
        *(float4*)&g_proj[rb]     = make_float4(acc[i][0], acc[i][1], acc[i][2], acc[i][3]);
        *(float4*)&g_proj[rb + 4] = make_float4(acc[i][4], acc[i][5], acc[i][6], acc[i][7]);
    }
}

// ---------------- two-level grid barrier -----------------------------------------
__device__ __forceinline__ void grid_barrier(unsigned int target) {
    __syncthreads();
    if (threadIdx.x == 0) {
        __threadfence();
        unsigned int tk = atomicAdd(&g_cnt[(blockIdx.x & 7) * 64], 1u);
        if ((tk & 15u) == 15u) {                 // last of 16 on this leaf, this round
            unsigned int f = atomicAdd(&g_fin, 1u);
            if ((f & 7u) == 7u) {                // last leaf of this round
                __threadfence();
                atomicAdd(&g_gen, 1u);
            }
        }
        while (*(volatile unsigned int*)&g_gen < target) { }
        __threadfence();
    }
    __syncthreads();
}

// ---------------- K2: scan --------------------------------------------------------
// 8 warps: kg = wid>>1 (K quarter = 2 chunks of K=128), mg = wid&1 (64 rows).
// A streamed as 8 chunks of 32KB through 4 slots. FULL[c] c=0..7 single-completion
// per step (parity l&1). Chunk c+4 (slot c&3) gated on CON[c] (count 2 = the two
// warps of kg=c>>1 that consumed chunk c). Cross-step slot reuse ordered by the
// grid barrier. W_hi in registers, W_lo in smem.
#define OFF_FULL   0       // FULL0..7 at 0..56
#define OFF_CON    64      // CON0..3 at 64..88
#define OFF_WLO    1024
#define OFF_SLOTS  33792   // 4 x 32768
#define OFF_RED    164864  // 2 x 128 x 33 x 4
#define SMEM_SCAN  (164864 + 2 * 128 * 33 * 4)

__global__ void __launch_bounds__(NT, 1)
scan_tc(const float* __restrict__ Wmm, const __grid_constant__ CUtensorMap tmap) {
    extern __shared__ char smem[];
    uint32_t sb = smem_u32(smem);
    float* RED = (float*)(smem + OFF_RED);
    uint2* Wlo = (uint2*)(smem + OFF_WLO);
    int t = threadIdx.x, wid = t >> 5, lane = t & 31;
    int kg = wid >> 1, mg = wid & 1;
    int j0 = blockIdx.x * JB;

    if (t == 0) {
#pragma unroll
        for (int c = 0; c < 8; c++) MBAR_INIT(sb + OFF_FULL + c * 8, 1);
#pragma unroll
        for (int c = 0; c < 4; c++) MBAR_INIT(sb + OFF_CON + c * 8, 2);
    }

    // W_hi fragments in registers (per-warp K quarter, n = a(8)|c(8))
    uint2 wf[16][2];
    {
        int jj = (lane >> 2) & 7;
#pragma unroll
        for (int kk = 0; kk < 16; kk++) {
            int k0 = kg * 256 + kk * 16 + (lane & 3) * 2;
            const float* wp = Wmm + (size_t)k0 * 2048;
#pragma unroll
            for (int np = 0; np < 2; np++) {
                int col = np * MEM + j0 + jj;
                wf[kk][np] = make_uint2(
                    packbf(wp[col], wp[2048 + col], false),
                    packbf(wp[8 * 2048 + col], wp[9 * 2048 + col], false));
            }
        }
    }
    // W_lo fragments in smem: [gk 64][np 2][lane 32]
    for (int idx = t; idx < 64 * 2 * 32; idx += NT) {
        int ln = idx & 31, np = (idx >> 5) & 1, gk = idx >> 6;
        int col = np * MEM + j0 + ((ln >> 2) & 7);
        int k0 = gk * 16 + (ln & 3) * 2;
        const float* wp = Wmm + (size_t)k0 * 2048;
        Wlo[idx] = make_uint2(
            packbf(wp[col], wp[2048 + col], true),
            packbf(wp[8 * 2048 + col], wp[9 * 2048 + col], true));
    }

    // init h
    float hreg[2] = {0.0f, 0.0f};
#pragma unroll
    for (int p = 0; p < 2; p++) {
        int idx = t + p * NT;
        int b = idx >> 3, jj = idx & 7, j = j0 + jj;
        g_hsplit[b * MEM + j]        = __float2bfloat16(0.0f);
        g_hsplit[(64 + b) * MEM + j] = __float2bfloat16(0.0f);
    }
    __syncthreads();

    unsigned int bar = 1;
    grid_barrier(bar);

    int redbar = 5 + (kg & 1);

    for (int l = 0; l < L_; l++) {
        int par = l & 1;
        // proj terms
        float ia[2], ic[2], io[2];
        size_t pb = (size_t)l * 3072 * 64;
#pragma unroll
        for (int p = 0; p < 2; p++) {
            int idx = t + p * NT;
            int b = idx >> 3, j = j0 + (idx & 7);
            ia[p] = __ldg(&g_proj[pb + (size_t)j * 64 + b]);
            ic[p] = __ldg(&g_proj[pb + (size_t)(MEM + j) * 64 + b]);
            io[p] = __ldg(&g_proj[pb + (size_t)(2 * MEM + j) * 64 + b]);
        }

        // producer: chunks 0..3 up-front (slot c; cross-step reuse ordered by barrier)
        if (t == 0) {
            FENCE_ASYNC_ALL();
#pragma unroll
            for (int c = 0; c < 4; c++) {
                MBAR_EXPECT_TX(sb + OFF_FULL + c * 8, 32768);
                TMA_LD(sb + OFF_SLOTS + c * 32768,          &tmap, c * 128,      0, 0, sb + OFF_FULL + c * 8);
                TMA_LD(sb + OFF_SLOTS + c * 32768 + 16384,  &tmap, c * 128 + 64, 0, 0, sb + OFF_FULL + c * 8);
            }
        }

        float acc[4][4][4];
#pragma unroll
        for (int a = 0; a < 4; a++)
#pragma unroll
            for (int b2 = 0; b2 < 4; b2++)
#pragma unroll
                for (int c = 0; c < 4; c++) acc[a][b2][c] = 0.0f;

        int lbase = (lane & 15) * 128 + ((lane >> 4) << 4);

        // two chunks per kg: global chunk ids 2kg, 2kg+1
#pragma unroll
        for (int ck = 0; ck < 2; ck++) {
            int c = 2 * kg + ck;
            uint32_t slot = sb + OFF_SLOTS + (uint32_t)(c & 3) * 32768u;
            MBAR_WAIT(sb + OFF_FULL + c * 8, par);
#pragma unroll
            for (int kk = 0; kk < 8; kk++) {
                int kt = ck * 8 + kk;
                uint2 blo0 = Wlo[((kg * 16 + kt) * 2 + 0) * 32 + lane];
                uint2 blo1 = Wlo[((kg * 16 + kt) * 2 + 1) * 32 + lane];
                uint32_t kbase = slot + (uint32_t)((kk >> 2) * 16384);
                uint32_t loff  = (uint32_t)SWZ(lbase + (kk & 3) * 32);
#pragma unroll
                for (int mt = 0; mt < 4; mt++) {
                    uint32_t addr = kbase + (uint32_t)((mg * 4 + mt) * 2048) + loff;
                    uint32_t a0, a1, a2, a3;
                    ldmatrix4(a0, a1, a2, a3, addr);
                    mma16816(acc[mt][0], a0, a1, a2, a3, wf[kt][0].x, wf[kt][0].y);
                    mma16816(acc[mt][1], a0, a1, a2, a3, wf[kt][1].x, wf[kt][1].y);
                    mma16816(acc[mt][2], a0, a1, a2, a3, blo0.x, blo0.y);
                    mma16816(acc[mt][3], a0, a1, a2, a3, blo1.x, blo1.y);
                }
            }
            // chunk consumed: kg0/kg1 gate the refills (chunks 4..7)
            if (kg < 2 && lane == 0) MBAR_ARRIVE(sb + OFF_CON + c * 8);
            // producer: refill slot c with chunk c+4 as soon as both consumers done
            if (t == 0 && ck == 0) {
                MBAR_WAIT(sb + OFF_CON + 0, par);
                MBAR_EXPECT_TX(sb + OFF_FULL + 4 * 8, 32768);
                TMA_LD(sb + OFF_SLOTS + 0 * 32768,         &tmap, 4 * 128,      0, 0, sb + OFF_FULL + 4 * 8);
                TMA_LD(sb + OFF_SLOTS + 0 * 32768 + 16384, &tmap, 4 * 128 + 64, 0, 0, sb + OFF_FULL + 4 * 8);
            }
        }
        if (t == 0) {
#pragma unroll
            for (int c = 5; c < 8; c++) {
                MBAR_WAIT(sb + OFF_CON + (c - 4) * 8, par);
                MBAR_EXPECT_TX(sb + OFF_FULL + c * 8, 32768);
                TMA_LD(sb + OFF_SLOTS + (c & 3) * 32768,         &tmap, c * 128,      0, 0, sb + OFF_FULL + c * 8);
                TMA_LD(sb + OFF_SLOTS + (c & 3) * 32768 + 16384, &tmap, c * 128 + 64, 0, 0, sb + OFF_FULL + c * 8);
            }
        }

        // RED: kg0/kg1 write, kg2/kg3 accumulate (ordered by named barrier)
        {
            float* rp = RED + (size_t)(kg & 1) * (128 * 33);
            int r0 = mg * 64 + (lane >> 2);
            int c0 = (lane & 3) * 2;
            if (kg < 2) {
#pragma unroll
                for (int mt = 0; mt < 4; mt++)
#pragma unroll
                    for (int np = 0; np < 4; np++) {
                        float* q = rp + (r0 + mt * 16) * 33 + np * 8 + c0;
                        q[0]          = acc[mt][np][0];
                        q[1]          = acc[mt][np][1];
                        q[8 * 33]     = acc[mt][np][2];
                        q[8 * 33 + 1] = acc[mt][np][3];
                    }
                BAR_ARRIVE(redbar, 128);
            } else {
                BAR_SYNC(redbar, 128);
#pragma unroll
                for (int mt = 0; mt < 4; mt++)
#pragma unroll
                    for (int np = 0; np < 4; np++) {
                        float* q = rp + (r0 + mt * 16) * 33 + np * 8 + c0;
                        q[0]          += acc[mt][np][0];
                        q[1]          += acc[mt][np][1];
                        q[8 * 33]     += acc[mt][np][2];
                        q[8 * 33 + 1] += acc[mt][np][3];
                    }
            }
        }
        __syncthreads();

        // combine + nBRC update
#pragma unroll
        for (int p = 0; p < 2; p++) {
            int idx = t + p * NT;
            int b = idx >> 3, jj = idx & 7, j = j0 + jj;
            float ma = 0.0f, mc = 0.0f;
#pragma unroll
            for (int q = 0; q < 2; q++) {
                const float* rq = RED + (size_t)q * (128 * 33);
                ma += rq[b * 33 + jj]          + rq[(64 + b) * 33 + jj]
                    + rq[b * 33 + 16 + jj]     + rq[(64 + b) * 33 + 16 + jj];
                mc += rq[b * 33 + 8 + jj]      + rq[(64 + b) * 33 + 8 + jj]
                    + rq[b * 33 + 24 + jj]     + rq[(64 + b) * 33 + 24 + jj];
            }
            float a  = 1.0f + tanh_acc(ia[p] + ma);
            float cg = sigmoid_acc(ic[p] + mc);
            float hn = cg * hreg[p] + (1.0f - cg) * tanh_acc(io[p] + a * hreg[p]);
            hreg[p] = hn;
            __nv_bfloat16 hh = __float2bfloat16(hn);
            __nv_bfloat16 hl = __float2bfloat16(hn - __bfloat162float(hh));
            g_hsplit[b * MEM + j]        = hh;
            g_hsplit[(64 + b) * MEM + j] = hl;
            g_mem[(size_t)l * (MEM * B_) + (size_t)j * B_ + b] = hn;
        }

        grid_barrier(++bar);
    }
}

// ---------------- K3: logits + softmax (4 timesteps/block) -----------------------
__global__ void __launch_bounds__(256) logits_kernel(const float* __restrict__ Wact,
                                                     const float* __restrict__ bact,
                                                     float* __restrict__ out) {
    __shared__ float Wa[MEM * DEC];
    int t = threadIdx.x;
    int l = blockIdx.x * 4 + (t >> 6);
    int b = t & 63;
    for (int idx = t; idx < MEM * DEC; idx += 256) Wa[idx] = Wact[idx];
    __syncthreads();

    float a0 = bact[0], a1 = bact[1], a2 = bact[2];
    const float* mp = g_mem + (size_t)l * MEM * B_ + b;
#pragma unroll 8
    for (int k = 0; k < MEM; k++) {
        float v = mp[(size_t)k * B_];
        a0 += v * Wa[k * 3 + 0];
        a1 += v * Wa[k * 3 + 1];
        a2 += v * Wa[k * 3 + 2];
    }
    float m  = fmaxf(a0, fmaxf(a1, a2));
    float e0 = __expf(a0 - m), e1 = __expf(a1 - m), e2 = __expf(a2 - m);
    float inv = 1.0f / (e0 + e1 + e2);
    size_t ob = ((size_t)b * L_ + l) * DEC;
    out[ob + 0] = e0 * inv;
    out[ob + 1] = e1 * inv;
    out[ob + 2] = e2 * inv;
}

// ---------------- launch ----------------------------------------------------------
typedef CUresult (*PFN_tmapEncode)(
    CUtensorMap*, CUtensorMapDataType, cuuint32_t, void*,
    const cuuint64_t*, const cuuint64_t*, const cuuint32_t*, const cuuint32_t*,
    CUtensorMapInterleave, CUtensorMapSwizzle, CUtensorMapL2promotion,
    CUtensorMapFloatOOBfill);

extern "C" void kernel_launch(void* const* d_in, const int* in_sizes, int n_in,
                              void* d_out, int out_size) {
    (void)in_sizes; (void)n_in; (void)out_size;
    const float* x   = (const float*)d_in[0];
    const float* Ws  = (const float*)d_in[1];
    const float* bs  = (const float*)d_in[2];
    const float* Wim = (const float*)d_in[3];
    const float* Wmm = (const float*)d_in[4];
    const float* Wac = (const float*)d_in[5];
    const float* bac = (const float*)d_in[6];
    float* out = (float*)d_out;

    void* hs_ptr = nullptr;
    cudaGetSymbolAddress(&hs_ptr, g_hsplit);
    PFN_tmapEncode enc = nullptr;
    cudaDriverEntryPointQueryResult qr;
    cudaGetDriverEntryPoint("cuTensorMapEncodeTiled", (void**)&enc,
                            cudaEnableDefault, &qr);
    CUtensorMap tmap;
    {
        cuuint64_t dims[3]    = {MEM, 128, 1};
        cuuint64_t strides[2] = {MEM * 2, (cuuint64_t)MEM * 2 * 128};
        cuuint32_t box[3]     = {64, 128, 1};
        cuuint32_t es[3]      = {1, 1, 1};
        enc(&tmap, CU_TENSOR_MAP_DATA_TYPE_BFLOAT16, 3, hs_ptr,
            dims, strides, box, es,
            CU_TENSOR_MAP_INTERLEAVE_NONE, CU_TENSOR_MAP_SWIZZLE_128B,
            CU_TENSOR_MAP_L2_PROMOTION_L2_128B, CU_TENSOR_MAP_FLOAT_OOB_FILL_NONE);
    }

    cudaFuncSetAttribute(proj_kernel, cudaFuncAttributeMaxDynamicSharedMemorySize, 98304);
    cudaFuncSetAttribute(scan_tc,     cudaFuncAttributeMaxDynamicSharedMemorySize, SMEM_SCAN);

    reset_kernel<<<1, 512>>>();
    sense_kernel<<<B_ * L_ / 8, 128>>>(x, Ws, bs);
    proj_kernel<<<dim3(L_, 24), 256, 98304>>>(Wim);
    scan_tc<<<NCTA, NT, SMEM_SCAN>>>(Wmm, tmap);
    logits_kernel<<<L_ / 4, 256>>>(Wac, bac, out);
}

// round 11
// speedup vs baseline: 1.1985x; 1.1873x over previous
#include <cuda.h>
#include <cuda_runtime.h>
#include <cuda_bf16.h>
#include <cuda_fp16.h>
#include <math.h>
#include <stdint.h>

#define B_    64
#define L_    1024
#define N_    64
#define INSZ  128
#define MEM   1024
#define DEC   3

#define NCTA  128
#define NT    512
#define JB    8

// ---------------- scratch ----------------------------------------------------
__device__ float g_inter[(size_t)L_ * B_ * INSZ];
__device__ float g_proj [(size_t)L_ * 3 * MEM * B_];          // [l][col][b]
__device__ __half g_hA  [64 * MEM];                           // h as fp16, [b][j]
__device__ float g_mem  [(size_t)L_ * MEM * B_];              // [l][j][b]
// two-level barrier state (monotonic; zeroed each launch)
__device__ unsigned int g_cnt[8 * 64];
__device__ unsigned int g_fin;
__device__ unsigned int g_gen;

// ---------------- PTX helpers ------------------------------------------------
__device__ __forceinline__ uint32_t smem_u32(const void* p) {
    uint32_t a;
    asm("{ .reg .u64 t; cvta.to.shared.u64 t, %1; cvt.u32.u64 %0, t; }" : "=r"(a) : "l"(p));
    return a;
}
#define SWZ(o) ((o) ^ (((o) >> 3) & 0x70))

#define MBAR_INIT(a, c) asm volatile("mbarrier.init.shared.b64 [%0], %1;" :: "r"((uint32_t)(a)), "r"((uint32_t)(c)) : "memory")
#define MBAR_EXPECT_TX(a, n) asm volatile("mbarrier.arrive.expect_tx.shared.b64 _, [%0], %1;" :: "r"((uint32_t)(a)), "r"((uint32_t)(n)) : "memory")

#define MBAR_WAIT(a, par) do { \
    uint32_t _m = (uint32_t)(a); uint32_t _p = (uint32_t)(par); uint32_t _d; \
    asm volatile("{\n\t.reg .pred p;\n\t" \
        "mbarrier.try_wait.parity.acquire.cta.shared::cta.b64 p, [%1], %2;\n\t" \
        "selp.b32 %0, 1, 0, p;\n\t}" : "=r"(_d) : "r"(_m), "r"(_p) : "memory"); \
    if (!_d) { \
        asm volatile("{\n\t.reg .pred P1;\n\tWL_%=:\n\t" \
            "mbarrier.try_wait.parity.acquire.cta.shared::cta.b64 P1, [%0], %1, 0x989680;\n\t" \
            "@P1 bra.uni WD_%=;\n\tbra.uni WL_%=;\n\tWD_%=:\n\t}" \
            :: "r"(_m), "r"(_p) : "memory"); \
    } } while (0)

#define TMA_LD(dst, tm, cx, cy, cz, mbar) \
    asm volatile("cp.async.bulk.tensor.3d.shared::cta.global.tile.mbarrier::complete_tx::bytes " \
        "[%0], [%1, {%2, %3, %4}], [%5];" \
        :: "r"((uint32_t)(dst)), "l"(tm), "r"((int32_t)(cx)), "r"((int32_t)(cy)), "r"((int32_t)(cz)), \
           "r"((uint32_t)(mbar)) : "memory")

#define FENCE_ASYNC_ALL() asm volatile("fence.proxy.async;" ::: "memory")
#define BAR_ARRIVE(id, cnt) asm volatile("bar.arrive %0, %1;" :: "r"(id), "r"(cnt) : "memory")
#define BAR_SYNC(id, cnt)   asm volatile("bar.sync %0, %1;"   :: "r"(id), "r"(cnt) : "memory")

__device__ __forceinline__ void ldmatrix4(uint32_t& a0, uint32_t& a1, uint32_t& a2, uint32_t& a3,
                                          uint32_t addr) {
    asm volatile("ldmatrix.sync.aligned.m8n8.x4.shared.b16 {%0,%1,%2,%3}, [%4];"
        : "=r"(a0), "=r"(a1), "=r"(a2), "=r"(a3) : "r"(addr));
}
__device__ __forceinline__ void mma16816h(float* d, uint32_t a0, uint32_t a1, uint32_t a2, uint32_t a3,
                                          uint32_t b0, uint32_t b1) {
    asm volatile("mma.sync.aligned.m16n8k16.row.col.f32.f16.f16.f32 "
        "{%0,%1,%2,%3}, {%4,%5,%6,%7}, {%8,%9}, {%0,%1,%2,%3};"
        : "+f"(d[0]), "+f"(d[1]), "+f"(d[2]), "+f"(d[3])
        : "r"(a0), "r"(a1), "r"(a2), "r"(a3), "r"(b0), "r"(b1));
}

__device__ __forceinline__ float tanh_acc(float x) {
    float ax = fabsf(x);
    float e  = __expf(-2.0f * ax);
    float t  = (1.0f - e) / (1.0f + e);
    return copysignf(t, x);
}
__device__ __forceinline__ float sigmoid_acc(float z) {
    return 1.0f / (1.0f + __expf(-z));
}
__device__ __forceinline__ uint32_t packh(float x, float y, bool lo) {
    __half xh = __float2half(x), yh = __float2half(y);
    if (lo) {
        xh = __float2half(x - __half2float(xh));
        yh = __float2half(y - __half2float(yh));
    }
    return ((uint32_t)__half_as_ushort(yh) << 16) | (uint32_t)__half_as_ushort(xh);
}

__global__ void reset_kernel() {
    int t = threadIdx.x;
    if (t < 512) g_cnt[t] = 0u;
    if (t == 0) { g_fin = 0u; g_gen = 0u; }
}

// ---------------- K1a: sense (8 tokens/block) ------------------------------------
__global__ void __launch_bounds__(128) sense_kernel(const float* __restrict__ x,
                                                    const float* __restrict__ Ws,
                                                    const float* __restrict__ bs) {
    __shared__ float xs[8][N_];
    int t = threadIdx.x;
    int bl0 = blockIdx.x * 8;
#pragma unroll
    for (int i = 0; i < 4; i++) {
        int idx = t + i * 128;
        xs[idx >> 6][idx & 63] = x[(size_t)bl0 * N_ + idx];
    }
    __syncthreads();
    float acc[8];
    float bias = bs[t];
#pragma unroll
    for (int i = 0; i < 8; i++) acc[i] = bias;
    for (int n = 0; n < N_; n++) {
        float w = Ws[n * INSZ + t];
#pragma unroll
        for (int i = 0; i < 8; i++) acc[i] += xs[i][n] * w;
    }
#pragma unroll
    for (int i = 0; i < 8; i++) {
        int bl = bl0 + i;
        int b = bl >> 10, l = bl & (L_ - 1);
        g_inter[((size_t)l * B_ + b) * INSZ + t] = acc[i];
    }
}

// ---------------- K1b: proj --------------------------------------------------------
#define CB 128
__global__ void __launch_bounds__(256) proj_kernel(const float* __restrict__ Wim) {
    extern __shared__ float sm[];
    float* As = sm;
    float* Bs = sm + INSZ * B_;
    int l  = blockIdx.x;
    int cb = blockIdx.y;
    int t  = threadIdx.x;

    for (int idx = t; idx < B_ * INSZ; idx += 256) {
        int b = idx >> 7, k = idx & 127;
        As[k * B_ + b] = g_inter[((size_t)l * B_ + b) * INSZ + k];
    }
    for (int idx = t; idx < INSZ * CB; idx += 256) {
        int k = idx >> 7, cc = idx & 127;
        Bs[k * CB + cc] = Wim[(size_t)k * (3 * MEM) + cb * CB + cc];
    }
    __syncthreads();

    int cg = t >> 3;
    int bg = t & 7;
    float acc[4][8];
#pragma unroll
    for (int i = 0; i < 4; i++)
#pragma unroll
        for (int j = 0; j < 8; j++) acc[i][j] = 0.0f;

    for (int k = 0; k < INSZ; k++) {
        float4 bv  = *(const float4*)&Bs[k * CB + cg * 4];
        float4 a0  = *(const float4*)&As[k * B_ + bg * 8];
        float4 a1  = *(const float4*)&As[k * B_ + bg * 8 + 4];
        float bb[4] = {bv.x, bv.y, bv.z, bv.w};
        float aa[8] = {a0.x, a0.y, a0.z, a0.w, a1.x, a1.y, a1.z, a1.w};
#pragma unroll
        for (int i = 0; i < 4; i++)
#pragma unroll
            for (int j = 0; j < 8; j++) acc[i][j] += bb[i] * aa[j];
    }

    size_t base = (size_t)l * (3 * MEM) * B_ + (size_t)(cb * CB) * B_;
#pragma unroll
    for (int i = 0; i < 4; i++) {
        size_t rb = base + (size_t)(cg * 4 + i) * B_ + bg * 8;
        *(float4*)&g_proj[rb]     = make_float4(acc[i][0], acc[i][1], acc[i][2], acc[i][3]);
        *(float4*)&g_proj[rb + 4] = make_float4(acc[i][4], acc[i][5], acc[i][6], acc[i][7]);
    }
}

// ---------------- two-level grid barrier -------------------------------------------
__device__ __forceinline__ void grid_barrier(unsigned int target) {
    __syncthreads();
    if (threadIdx.x == 0) {
        __threadfence();
        unsigned int tk = atomicAdd(&g_cnt[(blockIdx.x & 7) * 64], 1u);
        if ((tk & 15u) == 15u) {
            unsigned int f = atomicAdd(&g_fin, 1u);
            if ((f & 7u) == 7u) {
                __threadfence();
                atomicAdd(&g_gen, 1u);
            }
        }
        while (*(volatile unsigned int*)&g_gen < target) { }
        __threadfence();
    }
    __syncthreads();
}

// ---------------- K2: scan ----------------------------------------------------------
// A = h fp16 [64 x 1024]. 16 warps: kg = wid>>1 (K=128 chunk), mg = wid&1 (32 rows).
// All 8 chunks (16KB each) resident simultaneously -> no slot reuse within a step.
// FULL[c] single completion per step (parity l&1); cross-step reuse ordered by the
// grid barrier. W_hi (fp16) in registers, W_lo (fp16) in smem.
#define OFF_FULL   0       // FULL0..7 at 0..56
#define OFF_WLO    1024    // 32KB
#define OFF_SLOTS  33792   // 8 x 16384 = 128KB
#define OFF_RED    164864  // 4 x 64 x 33 x 4 = 33792
#define SMEM_SCAN  (164864 + 4 * 64 * 33 * 4)

__global__ void __launch_bounds__(NT, 1)
scan_tc(const float* __restrict__ Wmm, const __grid_constant__ CUtensorMap tmap) {
    extern __shared__ char smem[];
    uint32_t sb = smem_u32(smem);
    float* RED = (float*)(smem + OFF_RED);
    uint2* Wlo = (uint2*)(smem + OFF_WLO);
    int t = threadIdx.x, wid = t >> 5, lane = t & 31;
    int kg = wid >> 1, mg = wid & 1;
    int j0 = blockIdx.x * JB;

    if (t == 0) {
#pragma unroll
        for (int c = 0; c < 8; c++) MBAR_INIT(sb + OFF_FULL + c * 8, 1);
    }

    // W_hi fragments in registers: per warp K slice kg*128..+128, n = a(8)|c(8)
    uint2 wf[8][2];
    {
        int jj = (lane >> 2) & 7;
#pragma unroll
        for (int kk = 0; kk < 8; kk++) {
            int k0 = kg * 128 + kk * 16 + (lane & 3) * 2;
            const float* wp = Wmm + (size_t)k0 * 2048;
#pragma unroll
            for (int np = 0; np < 2; np++) {
                int col = np * MEM + j0 + jj;
                wf[kk][np] = make_uint2(
                    packh(wp[col], wp[2048 + col], false),
                    packh(wp[8 * 2048 + col], wp[9 * 2048 + col], false));
            }
        }
    }
    // W_lo fragments in smem: [gk 64][np 2][lane 32]
    for (int idx = t; idx < 64 * 2 * 32; idx += NT) {
        int ln = idx & 31, np = (idx >> 5) & 1, gk = idx >> 6;
        int col = np * MEM + j0 + ((ln >> 2) & 7);
        int k0 = gk * 16 + (ln & 3) * 2;
        const float* wp = Wmm + (size_t)k0 * 2048;
        Wlo[idx] = make_uint2(
            packh(wp[col], wp[2048 + col], true),
            packh(wp[8 * 2048 + col], wp[9 * 2048 + col], true));
    }

    // init h = 0 (fp16 zeros; each CTA writes full array once — idempotent)
    for (int idx = t; idx < 64 * MEM / 2; idx += NT)
        ((uint32_t*)g_hA)[idx] = 0u;
    float hreg = 0.0f;
    __syncthreads();

    unsigned int bar = 1;
    grid_barrier(bar);

    int b  = t >> 3;
    int jj = t & 7;
    int j  = j0 + jj;
    int q  = kg & 3;
    int redbar = 4 + q;
    uint32_t myfull = sb + OFF_FULL + kg * 8;
    uint32_t myslot = sb + OFF_SLOTS + (uint32_t)kg * 16384u;
    int lbase = (lane & 15) * 128 + ((lane >> 4) << 4);

    for (int l = 0; l < L_; l++) {
        int par = l & 1;
        // proj terms (prefetch; DRAM-latency hidden under TMA/MMA)
        size_t pb = (size_t)l * 3072 * 64;
        float ia = __ldg(&g_proj[pb + (size_t)j * 64 + b]);
        float ic = __ldg(&g_proj[pb + (size_t)(MEM + j) * 64 + b]);
        float io = __ldg(&g_proj[pb + (size_t)(2 * MEM + j) * 64 + b]);

        // producer: all 8 chunks up-front (2 boxes of 8KB each per chunk)
        if (t == 0) {
            FENCE_ASYNC_ALL();
#pragma unroll
            for (int c = 0; c < 8; c++) {
                MBAR_EXPECT_TX(sb + OFF_FULL + c * 8, 16384);
                TMA_LD(sb + OFF_SLOTS + c * 16384,        &tmap, c * 128,      0, 0, sb + OFF_FULL + c * 8);
                TMA_LD(sb + OFF_SLOTS + c * 16384 + 8192, &tmap, c * 128 + 64, 0, 0, sb + OFF_FULL + c * 8);
            }
        }

        float acc[2][4][4];
#pragma unroll
        for (int a = 0; a < 2; a++)
#pragma unroll
            for (int b2 = 0; b2 < 4; b2++)
#pragma unroll
                for (int c = 0; c < 4; c++) acc[a][b2][c] = 0.0f;

        MBAR_WAIT(myfull, par);

#pragma unroll
        for (int kk = 0; kk < 8; kk++) {
            uint2 blo0 = Wlo[((kg * 8 + kk) * 2 + 0) * 32 + lane];
            uint2 blo1 = Wlo[((kg * 8 + kk) * 2 + 1) * 32 + lane];
            uint32_t kbase = myslot + (uint32_t)((kk >> 2) * 8192);
            uint32_t loff  = (uint32_t)SWZ(lbase + (kk & 3) * 32);
#pragma unroll
            for (int mt = 0; mt < 2; mt++) {
                uint32_t addr = kbase + (uint32_t)((mg * 2 + mt) * 2048) + loff;
                uint32_t a0, a1, a2, a3;
                ldmatrix4(a0, a1, a2, a3, addr);
                mma16816h(acc[mt][0], a0, a1, a2, a3, wf[kk][0].x, wf[kk][0].y);
                mma16816h(acc[mt][1], a0, a1, a2, a3, wf[kk][1].x, wf[kk][1].y);
                mma16816h(acc[mt][2], a0, a1, a2, a3, blo0.x, blo0.y);
                mma16816h(acc[mt][3], a0, a1, a2, a3, blo1.x, blo1.y);
            }
        }

        // RED: kg<4 write into buffer q, kg>=4 accumulate (ordered by named barrier)
        {
            float* rp = RED + (size_t)q * (64 * 33);
            int r0 = mg * 32 + (lane >> 2);
            int c0 = (lane & 3) * 2;
            if (kg < 4) {
#pragma unroll
                for (int mt = 0; mt < 2; mt++)
#pragma unroll
                    for (int np = 0; np < 4; np++) {
                        float* qp = rp + (r0 + mt * 16) * 33 + np * 8 + c0;
                        qp[0]          = acc[mt][np][0];
                        qp[1]          = acc[mt][np][1];
                        qp[8 * 33]     = acc[mt][np][2];
                        qp[8 * 33 + 1] = acc[mt][np][3];
                    }
                BAR_ARRIVE(redbar, 128);
            } else {
                BAR_SYNC(redbar, 128);
#pragma unroll
                for (int mt = 0; mt < 2; mt++)
#pragma unroll
                    for (int np = 0; np < 4; np++) {
                        float* qp = rp + (r0 + mt * 16) * 33 + np * 8 + c0;
                        qp[0]          += acc[mt][np][0];
                        qp[1]          += acc[mt][np][1];
                        qp[8 * 33]     += acc[mt][np][2];
                        qp[8 * 33 + 1] += acc[mt][np][3];
                    }
            }
        }
        __syncthreads();

        // combine + nBRC update (one (b,jj) per thread)
        {
            float ma = 0.0f, mc = 0.0f;
#pragma unroll
            for (int qq = 0; qq < 4; qq++) {
                const float* rq = RED + (size_t)qq * (64 * 33);
                ma += rq[b * 33 + jj]     + rq[b * 33 + 16 + jj];
                mc += rq[b * 33 + 8 + jj] + rq[b * 33 + 24 + jj];
            }
            float a  = 1.0f + tanh_acc(ia + ma);
            float cg = sigmoid_acc(ic + mc);
            float hn = cg * hreg + (1.0f - cg) * tanh_acc(io + a * hreg);
            hreg = hn;
            g_hA[b * MEM + j] = __float2half(hn);
            g_mem[(size_t)l * (MEM * B_) + (size_t)j * B_ + b] = hn;
        }

        grid_barrier(++bar);
    }
}

// ---------------- K3: logits + softmax (4 timesteps/block) --------------------------
__global__ void __launch_bounds__(256) logits_kernel(const float* __restrict__ Wact,
                                                     const float* __restrict__ bact,
                                                     float* __restrict__ out) {
    __shared__ float Wa[MEM * DEC];
    int t = threadIdx.x;
    int l = blockIdx.x * 4 + (t >> 6);
    int b = t & 63;
    for (int idx = t; idx < MEM * DEC; idx += 256) Wa[idx] = Wact[idx];
    __syncthreads();

    float a0 = bact[0], a1 = bact[1], a2 = bact[2];
    const float* mp = g_mem + (size_t)l * MEM * B_ + b;
#pragma unroll 8
    for (int k = 0; k < MEM; k++) {
        float v = mp[(size_t)k * B_];
        a0 += v * Wa[k * 3 + 0];
        a1 += v * Wa[k * 3 + 1];
        a2 += v * Wa[k * 3 + 2];
    }
    float m  = fmaxf(a0, fmaxf(a1, a2));
    float e0 = __expf(a0 - m), e1 = __expf(a1 - m), e2 = __expf(a2 - m);
    float inv = 1.0f / (e0 + e1 + e2);
    size_t ob = ((size_t)b * L_ + l) * DEC;
    out[ob + 0] = e0 * inv;
    out[ob + 1] = e1 * inv;
    out[ob + 2] = e2 * inv;
}

// ---------------- launch --------------------------------------------------------------
typedef CUresult (*PFN_tmapEncode)(
    CUtensorMap*, CUtensorMapDataType, cuuint32_t, void*,
    const cuuint64_t*, const cuuint64_t*, const cuuint32_t*, const cuuint32_t*,
    CUtensorMapInterleave, CUtensorMapSwizzle, CUtensorMapL2promotion,
    CUtensorMapFloatOOBfill);

extern "C" void kernel_launch(void* const* d_in, const int* in_sizes, int n_in,
                              void* d_out, int out_size) {
    (void)in_sizes; (void)n_in; (void)out_size;
    const float* x   = (const float*)d_in[0];
    const float* Ws  = (const float*)d_in[1];
    const float* bs  = (const float*)d_in[2];
    const float* Wim = (const float*)d_in[3];
    const float* Wmm = (const float*)d_in[4];
    const float* Wac = (const float*)d_in[5];
    const float* bac = (const float*)d_in[6];
    float* out = (float*)d_out;

    void* hs_ptr = nullptr;
    cudaGetSymbolAddress(&hs_ptr, g_hA);
    PFN_tmapEncode enc = nullptr;
    cudaDriverEntryPointQueryResult qr;
    cudaGetDriverEntryPoint("cuTensorMapEncodeTiled", (void**)&enc,
                            cudaEnableDefault, &qr);
    CUtensorMap tmap;
    {
        cuuint64_t dims[3]    = {MEM, 64, 1};
        cuuint64_t strides[2] = {MEM * 2, (cuuint64_t)MEM * 2 * 64};
        cuuint32_t box[3]     = {64, 64, 1};
        cuuint32_t es[3]      = {1, 1, 1};
        enc(&tmap, CU_TENSOR_MAP_DATA_TYPE_FLOAT16, 3, hs_ptr,
            dims, strides, box, es,
            CU_TENSOR_MAP_INTERLEAVE_NONE, CU_TENSOR_MAP_SWIZZLE_128B,
            CU_TENSOR_MAP_L2_PROMOTION_L2_128B, CU_TENSOR_MAP_FLOAT_OOB_FILL_NONE);
    }

    cudaFuncSetAttribute(proj_kernel, cudaFuncAttributeMaxDynamicSharedMemorySize, 98304);
    cudaFuncSetAttribute(scan_tc,     cudaFuncAttributeMaxDynamicSharedMemorySize, SMEM_SCAN);

    reset_kernel<<<1, 512>>>();
    sense_kernel<<<B_ * L_ / 8, 128>>>(x, Ws, bs);
    proj_kernel<<<dim3(L_, 24), 256, 98304>>>(Wim);
    scan_tc<<<NCTA, NT, SMEM_SCAN>>>(Wmm, tmap);
    logits_kernel<<<L_ / 4, 256>>>(Wac, bac, out);
}

// round 12
// speedup vs baseline: 1.4401x; 1.2016x over previous
#include <cuda.h>
#include <cuda_runtime.h>
#include <cuda_bf16.h>
#include <cuda_fp16.h>
#include <math.h>
#include <stdint.h>

#define B_    64
#define L_    1024
#define N_    64
#define INSZ  128
#define MEM   1024
#define DEC   3

#define NCTA  128
#define NT    512
#define JB    8

// ---------------- scratch ----------------------------------------------------
__device__ __half g_ih  [(size_t)L_ * 2 * B_ * INSZ];         // [l][part hi/lo][b][k]
__device__ uint2  g_wfrag[24 * 16 * 512];                     // W_im fragments (1.5MB)
__device__ float g_proj [(size_t)L_ * 3 * MEM * B_];          // [l][col][b]
__device__ __half g_hA  [64 * MEM];                           // h as fp16, [b][j]
__device__ float g_mem  [(size_t)L_ * MEM * B_];              // [l][j][b]
__device__ unsigned int g_cnt[8 * 64];
__device__ unsigned int g_fin;
__device__ unsigned int g_gen;

// ---------------- PTX helpers ------------------------------------------------
__device__ __forceinline__ uint32_t smem_u32(const void* p) {
    uint32_t a;
    asm("{ .reg .u64 t; cvta.to.shared.u64 t, %1; cvt.u32.u64 %0, t; }" : "=r"(a) : "l"(p));
    return a;
}
#define SWZ(o) ((o) ^ (((o) >> 3) & 0x70))

#define MBAR_INIT(a, c) asm volatile("mbarrier.init.shared.b64 [%0], %1;" :: "r"((uint32_t)(a)), "r"((uint32_t)(c)) : "memory")
#define MBAR_EXPECT_TX(a, n) asm volatile("mbarrier.arrive.expect_tx.shared.b64 _, [%0], %1;" :: "r"((uint32_t)(a)), "r"((uint32_t)(n)) : "memory")

#define MBAR_WAIT(a, par) do { \
    uint32_t _m = (uint32_t)(a); uint32_t _p = (uint32_t)(par); uint32_t _d; \
    asm volatile("{\n\t.reg .pred p;\n\t" \
        "mbarrier.try_wait.parity.acquire.cta.shared::cta.b64 p, [%1], %2;\n\t" \
        "selp.b32 %0, 1, 0, p;\n\t}" : "=r"(_d) : "r"(_m), "r"(_p) : "memory"); \
    if (!_d) { \
        asm volatile("{\n\t.reg .pred P1;\n\tWL_%=:\n\t" \
            "mbarrier.try_wait.parity.acquire.cta.shared::cta.b64 P1, [%0], %1, 0x989680;\n\t" \
            "@P1 bra.uni WD_%=;\n\tbra.uni WL_%=;\n\tWD_%=:\n\t}" \
            :: "r"(_m), "r"(_p) : "memory"); \
    } } while (0)

#define TMA_LD(dst, tm, cx, cy, cz, mbar) \
    asm volatile("cp.async.bulk.tensor.3d.shared::cta.global.tile.mbarrier::complete_tx::bytes " \
        "[%0], [%1, {%2, %3, %4}], [%5];" \
        :: "r"((uint32_t)(dst)), "l"(tm), "r"((int32_t)(cx)), "r"((int32_t)(cy)), "r"((int32_t)(cz)), \
           "r"((uint32_t)(mbar)) : "memory")

#define FENCE_ASYNC_ALL() asm volatile("fence.proxy.async;" ::: "memory")
#define BAR_ARRIVE(id, cnt) asm volatile("bar.arrive %0, %1;" :: "r"(id), "r"(cnt) : "memory")
#define BAR_SYNC(id, cnt)   asm volatile("bar.sync %0, %1;"   :: "r"(id), "r"(cnt) : "memory")

__device__ __forceinline__ void ldmatrix4(uint32_t& a0, uint32_t& a1, uint32_t& a2, uint32_t& a3,
                                          uint32_t addr) {
    asm volatile("ldmatrix.sync.aligned.m8n8.x4.shared.b16 {%0,%1,%2,%3}, [%4];"
        : "=r"(a0), "=r"(a1), "=r"(a2), "=r"(a3) : "r"(addr));
}
__device__ __forceinline__ void mma16816h(float* d, uint32_t a0, uint32_t a1, uint32_t a2, uint32_t a3,
                                          uint32_t b0, uint32_t b1) {
    asm volatile("mma.sync.aligned.m16n8k16.row.col.f32.f16.f16.f32 "
        "{%0,%1,%2,%3}, {%4,%5,%6,%7}, {%8,%9}, {%0,%1,%2,%3};"
        : "+f"(d[0]), "+f"(d[1]), "+f"(d[2]), "+f"(d[3])
        : "r"(a0), "r"(a1), "r"(a2), "r"(a3), "r"(b0), "r"(b1));
}

__device__ __forceinline__ float tanh_acc(float x) {
    float ax = fabsf(x);
    float e  = __expf(-2.0f * ax);
    float t  = (1.0f - e) / (1.0f + e);
    return copysignf(t, x);
}
__device__ __forceinline__ float sigmoid_acc(float z) {
    return 1.0f / (1.0f + __expf(-z));
}
__device__ __forceinline__ uint32_t packh(float x, float y, bool lo) {
    __half xh = __float2half(x), yh = __float2half(y);
    if (lo) {
        xh = __float2half(x - __half2float(xh));
        yh = __float2half(y - __half2float(yh));
    }
    return ((uint32_t)__half_as_ushort(yh) << 16) | (uint32_t)__half_as_ushort(xh);
}

__global__ void reset_kernel() {
    int t = threadIdx.x;
    if (t < 512) g_cnt[t] = 0u;
    if (t == 0) { g_fin = 0u; g_gen = 0u; }
}

// ---------------- K1a: sense (8 tokens/block) -> fp16 hi/lo -----------------------
__global__ void __launch_bounds__(128) sense_kernel(const float* __restrict__ x,
                                                    const float* __restrict__ Ws,
                                                    const float* __restrict__ bs) {
    __shared__ float xs[8][N_];
    int t = threadIdx.x;
    int bl0 = blockIdx.x * 8;
#pragma unroll
    for (int i = 0; i < 4; i++) {
        int idx = t + i * 128;
        xs[idx >> 6][idx & 63] = x[(size_t)bl0 * N_ + idx];
    }
    __syncthreads();
    float acc[8];
    float bias = bs[t];
#pragma unroll
    for (int i = 0; i < 8; i++) acc[i] = bias;
    for (int n = 0; n < N_; n++) {
        float w = Ws[n * INSZ + t];
#pragma unroll
        for (int i = 0; i < 8; i++) acc[i] += xs[i][n] * w;
    }
#pragma unroll
    for (int i = 0; i < 8; i++) {
        int bl = bl0 + i;
        int b = bl >> 10, l = bl & (L_ - 1);
        __half hh = __float2half(acc[i]);
        __half hl = __float2half(acc[i] - __half2float(hh));
        g_ih[(((size_t)l * 2 + 0) * B_ + b) * INSZ + t] = hh;
        g_ih[(((size_t)l * 2 + 1) * B_ + b) * INSZ + t] = hl;
    }
}

// ---------------- K1b-pre: W_im fragments (hi 0-7, lo 8-15) -----------------------
__global__ void __launch_bounds__(256) wprep_kernel(const float* __restrict__ Wim) {
    int ntile = blockIdx.x;          // 0..23, 128 cols each
    int t = threadIdx.x;
    for (int q = t; q < 16 * 16 * 32; q += 256) {
        int lane = q & 31, n8 = (q >> 5) & 15, wsel = q >> 9;
        bool lo = wsel >= 8;
        int n = ntile * 128 + n8 * 8 + (lane >> 2);
        int k0 = (wsel & 7) * 16 + (lane & 3) * 2;
        const float* wp = Wim + (size_t)k0 * 3072 + n;
        g_wfrag[(size_t)ntile * 8192 + q] =
            make_uint2(packh(wp[0], wp[3072], lo),
                       packh(wp[8 * 3072], wp[9 * 3072], lo));
    }
}

// ---------------- K1b: proj via mma.sync -------------------------------------------
// out[l, ntile*128+col, b] ; K = [Ah|Al|Ah] x [Wh;Wh;Wl]. grid (24, 256), 128 thr.
#define PSM_WF 0
#define PSM_A  65536
#define PSM_ST 98304
#define PSM_TOT (98304 + 128 * 65 * 4)
__global__ void __launch_bounds__(128) proj_tc() {
    extern __shared__ char sm[];
    uint32_t sb = smem_u32(sm);
    const uint2* Wfs = (const uint2*)(sm + PSM_WF);
    float* St = (float*)(sm + PSM_ST);
    int ntile = blockIdx.x;
    int l0 = blockIdx.y * 4;
    int t = threadIdx.x, w = t >> 5, lane = t & 31;
    int mbase = (w & 1) * 2;        // m-tile pair
    int nbase = (w >> 1) * 8;       // 8 n8-frags

    // stage W fragments (8192 uint2 = 4096 uint4)
    {
        const uint4* wsrc = (const uint4*)(g_wfrag + (size_t)ntile * 8192);
#pragma unroll
        for (int i = 0; i < 32; i++)
            ((uint4*)(sm + PSM_WF))[t + i * 128] = wsrc[t + i * 128];
    }
    __syncthreads();

    for (int li = 0; li < 4; li++) {
        int l = l0 + li;
        // stage A (2 parts x 64 b x 128 k fp16, swizzled 128B rows of 64 fp16)
        const uint4* asrc = (const uint4*)(g_ih + (size_t)l * 2 * B_ * INSZ);
#pragma unroll
        for (int i = 0; i < 16; i++) {
            int q = t + i * 128;
            int part = q >> 10;
            int rb = (q >> 4) & 63;
            int k0 = (q & 15) * 8;
            uint32_t dst = (uint32_t)(PSM_A + part * 16384 + (k0 >> 6) * 8192)
                         + SWZ((uint32_t)(rb * 128 + (k0 & 63) * 2));
            *(uint4*)(sm + dst) = asrc[q];
        }
        __syncthreads();

        float acc[2][8][4];
#pragma unroll
        for (int a = 0; a < 2; a++)
#pragma unroll
            for (int b2 = 0; b2 < 8; b2++)
#pragma unroll
                for (int c = 0; c < 4; c++) acc[a][b2][c] = 0.0f;

#pragma unroll
        for (int gk = 0; gk < 24; gk++) {
            int part = (gk >= 8 && gk < 16) ? 1 : 0;
            int wsel = (gk < 8) ? gk : gk - 8;
            int kk = gk & 7;
            uint32_t a0[2], a1[2], a2[2], a3[2];
#pragma unroll
            for (int mt = 0; mt < 2; mt++) {
                uint32_t addr = sb + (uint32_t)(PSM_A + part * 16384 + (kk >> 2) * 8192)
                    + SWZ((uint32_t)(((mbase + mt) * 16 + (lane & 15)) * 128
                                     + ((lane >> 4) << 4) + (kk & 3) * 32));
                ldmatrix4(a0[mt], a1[mt], a2[mt], a3[mt], addr);
            }
#pragma unroll
            for (int nn = 0; nn < 8; nn++) {
                uint2 bv = Wfs[(size_t)(wsel * 16 + nbase + nn) * 32 + lane];
#pragma unroll
                for (int mt = 0; mt < 2; mt++)
                    mma16816h(acc[mt][nn], a0[mt], a1[mt], a2[mt], a3[mt], bv.x, bv.y);
            }
        }
        __syncthreads();   // previous St consumers done (global write loop below)

        // stage D into padded St[col][b]
        {
            int c0 = (lane & 3) * 2;
#pragma unroll
            for (int mt = 0; mt < 2; mt++) {
                int r0 = (mbase + mt) * 16 + (lane >> 2);
#pragma unroll
                for (int nn = 0; nn < 8; nn++) {
                    int col = (nbase + nn) * 8 + c0;
                    St[col * 65 + r0]           = acc[mt][nn][0];
                    St[(col + 1) * 65 + r0]     = acc[mt][nn][1];
                    St[col * 65 + r0 + 8]       = acc[mt][nn][2];
                    St[(col + 1) * 65 + r0 + 8] = acc[mt][nn][3];
                }
            }
        }
        __syncthreads();

        // coalesced write: g_proj[l][ntile*128 + col][b]
        {
            float* dst = g_proj + (size_t)l * 3072 * 64 + (size_t)ntile * 128 * 64;
#pragma unroll
            for (int i = 0; i < 64; i++) {
                int q = t + i * 128;
                dst[q] = St[(q >> 6) * 65 + (q & 63)];
            }
        }
        __syncthreads();
    }
}

// ---------------- two-level grid barrier -------------------------------------------
__device__ __forceinline__ void grid_barrier(unsigned int target) {
    __syncthreads();
    if (threadIdx.x == 0) {
        __threadfence();
        unsigned int tk = atomicAdd(&g_cnt[(blockIdx.x & 7) * 64], 1u);
        if ((tk & 15u) == 15u) {
            unsigned int f = atomicAdd(&g_fin, 1u);
            if ((f & 7u) == 7u) {
                __threadfence();
                atomicAdd(&g_gen, 1u);
            }
        }
        while (*(volatile unsigned int*)&g_gen < target) { }
        __threadfence();
    }
    __syncthreads();
}

// ---------------- K2: scan (unchanged from R11) ------------------------------------
#define OFF_FULL   0
#define OFF_WLO    1024
#define OFF_SLOTS  33792
#define OFF_RED    164864
#define SMEM_SCAN  (164864 + 4 * 64 * 33 * 4)

__global__ void __launch_bounds__(NT, 1)
scan_tc(const float* __restrict__ Wmm, const __grid_constant__ CUtensorMap tmap) {
    extern __shared__ char smem[];
    uint32_t sb = smem_u32(smem);
    float* RED = (float*)(smem + OFF_RED);
    uint2* Wlo = (uint2*)(smem + OFF_WLO);
    int t = threadIdx.x, wid = t >> 5, lane = t & 31;
    int kg = wid >> 1, mg = wid & 1;
    int j0 = blockIdx.x * JB;

    if (t == 0) {
#pragma unroll
        for (int c = 0; c < 8; c++) MBAR_INIT(sb + OFF_FULL + c * 8, 1);
    }

    uint2 wf[8][2];
    {
        int jj = (lane >> 2) & 7;
#pragma unroll
        for (int kk = 0; kk < 8; kk++) {
            int k0 = kg * 128 + kk * 16 + (lane & 3) * 2;
            const float* wp = Wmm + (size_t)k0 * 2048;
#pragma unroll
            for (int np = 0; np < 2; np++) {
                int col = np * MEM + j0 + jj;
                wf[kk][np] = make_uint2(
                    packh(wp[col], wp[2048 + col], false),
                    packh(wp[8 * 2048 + col], wp[9 * 2048 + col], false));
            }
        }
    }
    for (int idx = t; idx < 64 * 2 * 32; idx += NT) {
        int ln = idx & 31, np = (idx >> 5) & 1, gk = idx >> 6;
        int col = np * MEM + j0 + ((ln >> 2) & 7);
        int k0 = gk * 16 + (ln & 3) * 2;
        const float* wp = Wmm + (size_t)k0 * 2048;
        Wlo[idx] = make_uint2(
            packh(wp[col], wp[2048 + col], true),
            packh(wp[8 * 2048 + col], wp[9 * 2048 + col], true));
    }

    for (int idx = t; idx < 64 * MEM / 2; idx += NT)
        ((uint32_t*)g_hA)[idx] = 0u;
    float hreg = 0.0f;
    __syncthreads();

    unsigned int bar = 1;
    grid_barrier(bar);

    int b  = t >> 3;
    int jj = t & 7;
    int j  = j0 + jj;
    int q  = kg & 3;
    int redbar = 4 + q;
    uint32_t myfull = sb + OFF_FULL + kg * 8;
    uint32_t myslot = sb + OFF_SLOTS + (uint32_t)kg * 16384u;
    int lbase = (lane & 15) * 128 + ((lane >> 4) << 4);

    for (int l = 0; l < L_; l++) {
        int par = l & 1;
        size_t pb = (size_t)l * 3072 * 64;
        float ia = __ldg(&g_proj[pb + (size_t)j * 64 + b]);
        float ic = __ldg(&g_proj[pb + (size_t)(MEM + j) * 64 + b]);
        float io = __ldg(&g_proj[pb + (size_t)(2 * MEM + j) * 64 + b]);

        if (t == 0) {
            FENCE_ASYNC_ALL();
#pragma unroll
            for (int c = 0; c < 8; c++) {
                MBAR_EXPECT_TX(sb + OFF_FULL + c * 8, 16384);
                TMA_LD(sb + OFF_SLOTS + c * 16384,        &tmap, c * 128,      0, 0, sb + OFF_FULL + c * 8);
                TMA_LD(sb + OFF_SLOTS + c * 16384 + 8192, &tmap, c * 128 + 64, 0, 0, sb + OFF_FULL + c * 8);
            }
        }

        float acc[2][4][4];
#pragma unroll
        for (int a = 0; a < 2; a++)
#pragma unroll
            for (int b2 = 0; b2 < 4; b2++)
#pragma unroll
                for (int c = 0; c < 4; c++) acc[a][b2][c] = 0.0f;

        MBAR_WAIT(myfull, par);

#pragma unroll
        for (int kk = 0; kk < 8; kk++) {
            uint2 blo0 = Wlo[((kg * 8 + kk) * 2 + 0) * 32 + lane];
            uint2 blo1 = Wlo[((kg * 8 + kk) * 2 + 1) * 32 + lane];
            uint32_t kbase = myslot + (uint32_t)((kk >> 2) * 8192);
            uint32_t loff  = (uint32_t)SWZ(lbase + (kk & 3) * 32);
#pragma unroll
            for (int mt = 0; mt < 2; mt++) {
                uint32_t addr = kbase + (uint32_t)((mg * 2 + mt) * 2048) + loff;
                uint32_t a0, a1, a2, a3;
                ldmatrix4(a0, a1, a2, a3, addr);
                mma16816h(acc[mt][0], a0, a1, a2, a3, wf[kk][0].x, wf[kk][0].y);
                mma16816h(acc[mt][1], a0, a1, a2, a3, wf[kk][1].x, wf[kk][1].y);
                mma16816h(acc[mt][2], a0, a1, a2, a3, blo0.x, blo0.y);
                mma16816h(acc[mt][3], a0, a1, a2, a3, blo1.x, blo1.y);
            }
        }

        {
            float* rp = RED + (size_t)q * (64 * 33);
            int r0 = mg * 32 + (lane >> 2);
            int c0 = (lane & 3) * 2;
            if (kg < 4) {
#pragma unroll
                for (int mt = 0; mt < 2; mt++)
#pragma unroll
                    for (int np = 0; np < 4; np++) {
                        float* qp = rp + (r0 + mt * 16) * 33 + np * 8 + c0;
                        qp[0]          = acc[mt][np][0];
                        qp[1]          = acc[mt][np][1];
                        qp[8 * 33]     = acc[mt][np][2];
                        qp[8 * 33 + 1] = acc[mt][np][3];
                    }
                BAR_ARRIVE(redbar, 128);
            } else {
                BAR_SYNC(redbar, 128);
#pragma unroll
                for (int mt = 0; mt < 2; mt++)
#pragma unroll
                    for (int np = 0; np < 4; np++) {
                        float* qp = rp + (r0 + mt * 16) * 33 + np * 8 + c0;
                        qp[0]          += acc[mt][np][0];
                        qp[1]          += acc[mt][np][1];
                        qp[8 * 33]     += acc[mt][np][2];
                        qp[8 * 33 + 1] += acc[mt][np][3];
                    }
            }
        }
        __syncthreads();

        {
            float ma = 0.0f, mc = 0.0f;
#pragma unroll
            for (int qq = 0; qq < 4; qq++) {
                const float* rq = RED + (size_t)qq * (64 * 33);
                ma += rq[b * 33 + jj]     + rq[b * 33 + 16 + jj];
                mc += rq[b * 33 + 8 + jj] + rq[b * 33 + 24 + jj];
            }
            float a  = 1.0f + tanh_acc(ia + ma);
            float cg = sigmoid_acc(ic + mc);
            float hn = cg * hreg + (1.0f - cg) * tanh_acc(io + a * hreg);
            hreg = hn;
            g_hA[b * MEM + j] = __float2half(hn);
            g_mem[(size_t)l * (MEM * B_) + (size_t)j * B_ + b] = hn;
        }

        grid_barrier(++bar);
    }
}

// ---------------- K3: logits + softmax (4 timesteps/block) --------------------------
__global__ void __launch_bounds__(256) logits_kernel(const float* __restrict__ Wact,
                                                     const float* __restrict__ bact,
                                                     float* __restrict__ out) {
    __shared__ float Wa[MEM * DEC];
    int t = threadIdx.x;
    int l = blockIdx.x * 4 + (t >> 6);
    int b = t & 63;
    for (int idx = t; idx < MEM * DEC; idx += 256) Wa[idx] = Wact[idx];
    __syncthreads();

    float a0 = bact[0], a1 = bact[1], a2 = bact[2];
    const float* mp = g_mem + (size_t)l * MEM * B_ + b;
#pragma unroll 8
    for (int k = 0; k < MEM; k++) {
        float v = mp[(size_t)k * B_];
        a0 += v * Wa[k * 3 + 0];
        a1 += v * Wa[k * 3 + 1];
        a2 += v * Wa[k * 3 + 2];
    }
    float m  = fmaxf(a0, fmaxf(a1, a2));
    float e0 = __expf(a0 - m), e1 = __expf(a1 - m), e2 = __expf(a2 - m);
    float inv = 1.0f / (e0 + e1 + e2);
    size_t ob = ((size_t)b * L_ + l) * DEC;
    out[ob + 0] = e0 * inv;
    out[ob + 1] = e1 * inv;
    out[ob + 2] = e2 * inv;
}

// ---------------- launch --------------------------------------------------------------
typedef CUresult (*PFN_tmapEncode)(
    CUtensorMap*, CUtensorMapDataType, cuuint32_t, void*,
    const cuuint64_t*, const cuuint64_t*, const cuuint32_t*, const cuuint32_t*,
    CUtensorMapInterleave, CUtensorMapSwizzle, CUtensorMapL2promotion,
    CUtensorMapFloatOOBfill);

extern "C" void kernel_launch(void* const* d_in, const int* in_sizes, int n_in,
                              void* d_out, int out_size) {
    (void)in_sizes; (void)n_in; (void)out_size;
    const float* x   = (const float*)d_in[0];
    const float* Ws  = (const float*)d_in[1];
    const float* bs  = (const float*)d_in[2];
    const float* Wim = (const float*)d_in[3];
    const float* Wmm = (const float*)d_in[4];
    const float* Wac = (const float*)d_in[5];
    const float* bac = (const float*)d_in[6];
    float* out = (float*)d_out;

    void* hs_ptr = nullptr;
    cudaGetSymbolAddress(&hs_ptr, g_hA);
    PFN_tmapEncode enc = nullptr;
    cudaDriverEntryPointQueryResult qr;
    cudaGetDriverEntryPoint("cuTensorMapEncodeTiled", (void**)&enc,
                            cudaEnableDefault, &qr);
    CUtensorMap tmap;
    {
        cuuint64_t dims[3]    = {MEM, 64, 1};
        cuuint64_t strides[2] = {MEM * 2, (cuuint64_t)MEM * 2 * 64};
        cuuint32_t box[3]     = {64, 64, 1};
        cuuint32_t es[3]      = {1, 1, 1};
        enc(&tmap, CU_TENSOR_MAP_DATA_TYPE_FLOAT16, 3, hs_ptr,
            dims, strides, box, es,
            CU_TENSOR_MAP_INTERLEAVE_NONE, CU_TENSOR_MAP_SWIZZLE_128B,
            CU_TENSOR_MAP_L2_PROMOTION_L2_128B, CU_TENSOR_MAP_FLOAT_OOB_FILL_NONE);
    }

    cudaFuncSetAttribute(proj_tc,  cudaFuncAttributeMaxDynamicSharedMemorySize, PSM_TOT);
    cudaFuncSetAttribute(scan_tc,  cudaFuncAttributeMaxDynamicSharedMemorySize, SMEM_SCAN);

    reset_kernel<<<1, 512>>>();
    sense_kernel<<<B_ * L_ / 8, 128>>>(x, Ws, bs);
    wprep_kernel<<<24, 256>>>(Wim);
    proj_tc<<<dim3(24, 256), 128, PSM_TOT>>>();
    scan_tc<<<NCTA, NT, SMEM_SCAN>>>(Wmm, tmap);
    logits_kernel<<<L_ / 4, 256>>>(Wac, bac, out);
}

// round 13
// speedup vs baseline: 1.8490x; 1.2839x over previous
#include <cuda.h>
#include <cuda_runtime.h>
#include <cuda_bf16.h>
#include <cuda_fp16.h>
#include <math.h>
#include <stdint.h>

#define B_    64
#define L_    1024
#define N_    64
#define INSZ  128
#define MEM   1024
#define DEC   3

#define NCTA  128
#define NT    512
#define JB    8

// ---------------- scratch ----------------------------------------------------
__device__ __half g_ih  [(size_t)L_ * 2 * B_ * INSZ];         // [l][part hi/lo][b][k]
__device__ uint2  g_wfrag[24 * 16 * 512];                     // W_im fragments (1.5MB)
__device__ float g_proj [(size_t)L_ * 3 * MEM * B_];          // [l][col][b]
__device__ __half g_hA  [2 * 64 * MEM];                       // double-buffered h fp16 [buf][b][j]
__device__ float g_mem  [(size_t)L_ * MEM * B_];              // [l][j][b]
__device__ unsigned int g_grp[8 * 64];                        // per-group monotonic counters

// ---------------- PTX helpers ------------------------------------------------
__device__ __forceinline__ uint32_t smem_u32(const void* p) {
    uint32_t a;
    asm("{ .reg .u64 t; cvta.to.shared.u64 t, %1; cvt.u32.u64 %0, t; }" : "=r"(a) : "l"(p));
    return a;
}
#define SWZ(o) ((o) ^ (((o) >> 3) & 0x70))

#define MBAR_INIT(a, c) asm volatile("mbarrier.init.shared.b64 [%0], %1;" :: "r"((uint32_t)(a)), "r"((uint32_t)(c)) : "memory")
#define MBAR_EXPECT_TX(a, n) asm volatile("mbarrier.arrive.expect_tx.shared.b64 _, [%0], %1;" :: "r"((uint32_t)(a)), "r"((uint32_t)(n)) : "memory")

#define MBAR_WAIT(a, par) do { \
    uint32_t _m = (uint32_t)(a); uint32_t _p = (uint32_t)(par); uint32_t _d; \
    asm volatile("{\n\t.reg .pred p;\n\t" \
        "mbarrier.try_wait.parity.acquire.cta.shared::cta.b64 p, [%1], %2;\n\t" \
        "selp.b32 %0, 1, 0, p;\n\t}" : "=r"(_d) : "r"(_m), "r"(_p) : "memory"); \
    if (!_d) { \
        asm volatile("{\n\t.reg .pred P1;\n\tWL_%=:\n\t" \
            "mbarrier.try_wait.parity.acquire.cta.shared::cta.b64 P1, [%0], %1, 0x989680;\n\t" \
            "@P1 bra.uni WD_%=;\n\tbra.uni WL_%=;\n\tWD_%=:\n\t}" \
            :: "r"(_m), "r"(_p) : "memory"); \
    } } while (0)

#define TMA_LD(dst, tm, cx, cy, cz, mbar) \
    asm volatile("cp.async.bulk.tensor.3d.shared::cta.global.tile.mbarrier::complete_tx::bytes " \
        "[%0], [%1, {%2, %3, %4}], [%5];" \
        :: "r"((uint32_t)(dst)), "l"(tm), "r"((int32_t)(cx)), "r"((int32_t)(cy)), "r"((int32_t)(cz)), \
           "r"((uint32_t)(mbar)) : "memory")

#define FENCE_ASYNC_ALL() asm volatile("fence.proxy.async;" ::: "memory")
#define BAR_ARRIVE(id, cnt) asm volatile("bar.arrive %0, %1;" :: "r"(id), "r"(cnt) : "memory")
#define BAR_SYNC(id, cnt)   asm volatile("bar.sync %0, %1;"   :: "r"(id), "r"(cnt) : "memory")

__device__ __forceinline__ void ldmatrix4(uint32_t& a0, uint32_t& a1, uint32_t& a2, uint32_t& a3,
                                          uint32_t addr) {
    asm volatile("ldmatrix.sync.aligned.m8n8.x4.shared.b16 {%0,%1,%2,%3}, [%4];"
        : "=r"(a0), "=r"(a1), "=r"(a2), "=r"(a3) : "r"(addr));
}
__device__ __forceinline__ void mma16816h(float* d, uint32_t a0, uint32_t a1, uint32_t a2, uint32_t a3,
                                          uint32_t b0, uint32_t b1) {
    asm volatile("mma.sync.aligned.m16n8k16.row.col.f32.f16.f16.f32 "
        "{%0,%1,%2,%3}, {%4,%5,%6,%7}, {%8,%9}, {%0,%1,%2,%3};"
        : "+f"(d[0]), "+f"(d[1]), "+f"(d[2]), "+f"(d[3])
        : "r"(a0), "r"(a1), "r"(a2), "r"(a3), "r"(b0), "r"(b1));
}

__device__ __forceinline__ float tanh_acc(float x) {
    float ax = fabsf(x);
    float e  = __expf(-2.0f * ax);
    float t  = (1.0f - e) / (1.0f + e);
    return copysignf(t, x);
}
__device__ __forceinline__ float sigmoid_acc(float z) {
    return 1.0f / (1.0f + __expf(-z));
}
__device__ __forceinline__ uint32_t packh(float x, float y, bool lo) {
    __half xh = __float2half(x), yh = __float2half(y);
    if (lo) {
        xh = __float2half(x - __half2float(xh));
        yh = __float2half(y - __half2float(yh));
    }
    return ((uint32_t)__half_as_ushort(yh) << 16) | (uint32_t)__half_as_ushort(xh);
}

__global__ void reset_kernel() {
    int t = threadIdx.x;
    if (t < 512) g_grp[t] = 0u;
}

// ---------------- K1a: sense (8 tokens/block) -> fp16 hi/lo -----------------------
__global__ void __launch_bounds__(128) sense_kernel(const float* __restrict__ x,
                                                    const float* __restrict__ Ws,
                                                    const float* __restrict__ bs) {
    __shared__ float xs[8][N_];
    int t = threadIdx.x;
    int bl0 = blockIdx.x * 8;
#pragma unroll
    for (int i = 0; i < 4; i++) {
        int idx = t + i * 128;
        xs[idx >> 6][idx & 63] = x[(size_t)bl0 * N_ + idx];
    }
    __syncthreads();
    float acc[8];
    float bias = bs[t];
#pragma unroll
    for (int i = 0; i < 8; i++) acc[i] = bias;
    for (int n = 0; n < N_; n++) {
        float w = Ws[n * INSZ + t];
#pragma unroll
        for (int i = 0; i < 8; i++) acc[i] += xs[i][n] * w;
    }
#pragma unroll
    for (int i = 0; i < 8; i++) {
        int bl = bl0 + i;
        int b = bl >> 10, l = bl & (L_ - 1);
        __half hh = __float2half(acc[i]);
        __half hl = __float2half(acc[i] - __half2float(hh));
        g_ih[(((size_t)l * 2 + 0) * B_ + b) * INSZ + t] = hh;
        g_ih[(((size_t)l * 2 + 1) * B_ + b) * INSZ + t] = hl;
    }
}

// ---------------- K1b-pre: W_im fragments -----------------------------------------
__global__ void __launch_bounds__(256) wprep_kernel(const float* __restrict__ Wim) {
    int ntile = blockIdx.x;
    int t = threadIdx.x;
    for (int q = t; q < 16 * 16 * 32; q += 256) {
        int lane = q & 31, n8 = (q >> 5) & 15, wsel = q >> 9;
        bool lo = wsel >= 8;
        int n = ntile * 128 + n8 * 8 + (lane >> 2);
        int k0 = (wsel & 7) * 16 + (lane & 3) * 2;
        const float* wp = Wim + (size_t)k0 * 3072 + n;
        g_wfrag[(size_t)ntile * 8192 + q] =
            make_uint2(packh(wp[0], wp[3072], lo),
                       packh(wp[8 * 3072], wp[9 * 3072], lo));
    }
}

// ---------------- K1b: proj via mma.sync (unchanged from R12) ----------------------
#define PSM_WF 0
#define PSM_A  65536
#define PSM_ST 98304
#define PSM_TOT (98304 + 128 * 65 * 4)
__global__ void __launch_bounds__(128) proj_tc() {
    extern __shared__ char sm[];
    uint32_t sb = smem_u32(sm);
    const uint2* Wfs = (const uint2*)(sm + PSM_WF);
    float* St = (float*)(sm + PSM_ST);
    int ntile = blockIdx.x;
    int l0 = blockIdx.y * 4;
    int t = threadIdx.x, w = t >> 5, lane = t & 31;
    int mbase = (w & 1) * 2;
    int nbase = (w >> 1) * 8;

    {
        const uint4* wsrc = (const uint4*)(g_wfrag + (size_t)ntile * 8192);
#pragma unroll
        for (int i = 0; i < 32; i++)
            ((uint4*)(sm + PSM_WF))[t + i * 128] = wsrc[t + i * 128];
    }
    __syncthreads();

    for (int li = 0; li < 4; li++) {
        int l = l0 + li;
        const uint4* asrc = (const uint4*)(g_ih + (size_t)l * 2 * B_ * INSZ);
#pragma unroll
        for (int i = 0; i < 16; i++) {
            int q = t + i * 128;
            int part = q >> 10;
            int rb = (q >> 4) & 63;
            int k0 = (q & 15) * 8;
            uint32_t dst = (uint32_t)(PSM_A + part * 16384 + (k0 >> 6) * 8192)
                         + SWZ((uint32_t)(rb * 128 + (k0 & 63) * 2));
            *(uint4*)(sm + dst) = asrc[q];
        }
        __syncthreads();

        float acc[2][8][4];
#pragma unroll
        for (int a = 0; a < 2; a++)
#pragma unroll
            for (int b2 = 0; b2 < 8; b2++)
#pragma unroll
                for (int c = 0; c < 4; c++) acc[a][b2][c] = 0.0f;

#pragma unroll
        for (int gk = 0; gk < 24; gk++) {
            int part = (gk >= 8 && gk < 16) ? 1 : 0;
            int wsel = (gk < 8) ? gk : gk - 8;
            int kk = gk & 7;
            uint32_t a0[2], a1[2], a2[2], a3[2];
#pragma unroll
            for (int mt = 0; mt < 2; mt++) {
                uint32_t addr = sb + (uint32_t)(PSM_A + part * 16384 + (kk >> 2) * 8192)
                    + SWZ((uint32_t)(((mbase + mt) * 16 + (lane & 15)) * 128
                                     + ((lane >> 4) << 4) + (kk & 3) * 32));
                ldmatrix4(a0[mt], a1[mt], a2[mt], a3[mt], addr);
            }
#pragma unroll
            for (int nn = 0; nn < 8; nn++) {
                uint2 bv = Wfs[(size_t)(wsel * 16 + nbase + nn) * 32 + lane];
#pragma unroll
                for (int mt = 0; mt < 2; mt++)
                    mma16816h(acc[mt][nn], a0[mt], a1[mt], a2[mt], a3[mt], bv.x, bv.y);
            }
        }
        __syncthreads();

        {
            int c0 = (lane & 3) * 2;
#pragma unroll
            for (int mt = 0; mt < 2; mt++) {
                int r0 = (mbase + mt) * 16 + (lane >> 2);
#pragma unroll
                for (int nn = 0; nn < 8; nn++) {
                    int col = (nbase + nn) * 8 + c0;
                    St[col * 65 + r0]           = acc[mt][nn][0];
                    St[(col + 1) * 65 + r0]     = acc[mt][nn][1];
                    St[col * 65 + r0 + 8]       = acc[mt][nn][2];
                    St[(col + 1) * 65 + r0 + 8] = acc[mt][nn][3];
                }
            }
        }
        __syncthreads();

        {
            float* dst = g_proj + (size_t)l * 3072 * 64 + (size_t)ntile * 128 * 64;
#pragma unroll
            for (int i = 0; i < 64; i++) {
                int q = t + i * 128;
                dst[q] = St[(q >> 6) * 65 + (q & 63)];
            }
        }
        __syncthreads();
    }
}

// ---------------- K2: scan with per-group counters ---------------------------------
// Group g = blockIdx.x>>4 owns A chunk g (k cols g*128..+128, written by its 16 CTAs).
// End of step: CTA arrives on its group counter (monotonic). Each kg's mg0-lane0 warp
// polls counter kg >= 16*(l+1), then issues chunk kg's TMAs itself. h double-buffered.
#define OFF_FULL   0
#define OFF_WLO    1024
#define OFF_SLOTS  33792
#define OFF_RED    164864
#define SMEM_SCAN  (164864 + 4 * 64 * 33 * 4)

__global__ void __launch_bounds__(NT, 1)
scan_tc(const float* __restrict__ Wmm, const __grid_constant__ CUtensorMap tmap) {
    extern __shared__ char smem[];
    uint32_t sb = smem_u32(smem);
    float* RED = (float*)(smem + OFF_RED);
    uint2* Wlo = (uint2*)(smem + OFF_WLO);
    int t = threadIdx.x, wid = t >> 5, lane = t & 31;
    int kg = wid >> 1, mg = wid & 1;
    int j0 = blockIdx.x * JB;
    int mygrp = blockIdx.x >> 4;

    if (t == 0) {
#pragma unroll
        for (int c = 0; c < 8; c++) MBAR_INIT(sb + OFF_FULL + c * 8, 1);
    }

    // W_hi fragments in registers
    uint2 wf[8][2];
    {
        int jj = (lane >> 2) & 7;
#pragma unroll
        for (int kk = 0; kk < 8; kk++) {
            int k0 = kg * 128 + kk * 16 + (lane & 3) * 2;
            const float* wp = Wmm + (size_t)k0 * 2048;
#pragma unroll
            for (int np = 0; np < 2; np++) {
                int col = np * MEM + j0 + jj;
                wf[kk][np] = make_uint2(
                    packh(wp[col], wp[2048 + col], false),
                    packh(wp[8 * 2048 + col], wp[9 * 2048 + col], false));
            }
        }
    }
    // W_lo fragments in smem
    for (int idx = t; idx < 64 * 2 * 32; idx += NT) {
        int ln = idx & 31, np = (idx >> 5) & 1, gk = idx >> 6;
        int col = np * MEM + j0 + ((ln >> 2) & 7);
        int k0 = gk * 16 + (ln & 3) * 2;
        const float* wp = Wmm + (size_t)k0 * 2048;
        Wlo[idx] = make_uint2(
            packh(wp[col], wp[2048 + col], true),
            packh(wp[8 * 2048 + col], wp[9 * 2048 + col], true));
    }

    // init h = 0 into buffer 0 (own columns only)
    int b  = t >> 3;
    int jj = t & 7;
    int j  = j0 + jj;
    g_hA[b * MEM + j] = __float2half(0.0f);
    float hreg = 0.0f;
    __syncthreads();
    if (t == 0) {
        __threadfence();
        atomicAdd(&g_grp[mygrp * 64], 1u);       // level 1
    }

    int q  = kg & 3;
    int redbar = 4 + q;
    uint32_t myfull = sb + OFF_FULL + kg * 8;
    uint32_t myslot = sb + OFF_SLOTS + (uint32_t)kg * 16384u;
    int lbase = (lane & 15) * 128 + ((lane >> 4) << 4);
    volatile unsigned int* mycnt = (volatile unsigned int*)&g_grp[kg * 64];

    for (int l = 0; l < L_; l++) {
        int par = l & 1;
        size_t pb = (size_t)l * 3072 * 64;
        float ia = __ldg(&g_proj[pb + (size_t)j * 64 + b]);
        float ic = __ldg(&g_proj[pb + (size_t)(MEM + j) * 64 + b]);
        float io = __ldg(&g_proj[pb + (size_t)(2 * MEM + j) * 64 + b]);

        // JIT producer: mg0-lane0 of each kg polls its group and issues its chunk
        if (mg == 0 && lane == 0) {
            unsigned int tgt = 16u * (unsigned int)(l + 1);
            while (*mycnt < tgt) { }
            __threadfence();
            FENCE_ASYNC_ALL();
            MBAR_EXPECT_TX(myfull, 16384);
            TMA_LD(myslot,        &tmap, kg * 128,      par * 64, 0, myfull);
            TMA_LD(myslot + 8192, &tmap, kg * 128 + 64, par * 64, 0, myfull);
        }

        float acc[2][4][4];
#pragma unroll
        for (int a = 0; a < 2; a++)
#pragma unroll
            for (int b2 = 0; b2 < 4; b2++)
#pragma unroll
                for (int c = 0; c < 4; c++) acc[a][b2][c] = 0.0f;

        MBAR_WAIT(myfull, par);

#pragma unroll
        for (int kk = 0; kk < 8; kk++) {
            uint2 blo0 = Wlo[((kg * 8 + kk) * 2 + 0) * 32 + lane];
            uint2 blo1 = Wlo[((kg * 8 + kk) * 2 + 1) * 32 + lane];
            uint32_t kbase = myslot + (uint32_t)((kk >> 2) * 8192);
            uint32_t loff  = (uint32_t)SWZ(lbase + (kk & 3) * 32);
#pragma unroll
            for (int mt = 0; mt < 2; mt++) {
                uint32_t addr = kbase + (uint32_t)((mg * 2 + mt) * 2048) + loff;
                uint32_t a0, a1, a2, a3;
                ldmatrix4(a0, a1, a2, a3, addr);
                mma16816h(acc[mt][0], a0, a1, a2, a3, wf[kk][0].x, wf[kk][0].y);
                mma16816h(acc[mt][1], a0, a1, a2, a3, wf[kk][1].x, wf[kk][1].y);
                mma16816h(acc[mt][2], a0, a1, a2, a3, blo0.x, blo0.y);
                mma16816h(acc[mt][3], a0, a1, a2, a3, blo1.x, blo1.y);
            }
        }

        // RED: kg<4 write into buffer q, kg>=4 accumulate
        {
            float* rp = RED + (size_t)q * (64 * 33);
            int r0 = mg * 32 + (lane >> 2);
            int c0 = (lane & 3) * 2;
            if (kg < 4) {
#pragma unroll
                for (int mt = 0; mt < 2; mt++)
#pragma unroll
                    for (int np = 0; np < 4; np++) {
                        float* qp = rp + (r0 + mt * 16) * 33 + np * 8 + c0;
                        qp[0]          = acc[mt][np][0];
                        qp[1]          = acc[mt][np][1];
                        qp[8 * 33]     = acc[mt][np][2];
                        qp[8 * 33 + 1] = acc[mt][np][3];
                    }
                BAR_ARRIVE(redbar, 128);
            } else {
                BAR_SYNC(redbar, 128);
#pragma unroll
                for (int mt = 0; mt < 2; mt++)
#pragma unroll
                    for (int np = 0; np < 4; np++) {
                        float* qp = rp + (r0 + mt * 16) * 33 + np * 8 + c0;
                        qp[0]          += acc[mt][np][0];
                        qp[1]          += acc[mt][np][1];
                        qp[8 * 33]     += acc[mt][np][2];
                        qp[8 * 33 + 1] += acc[mt][np][3];
                    }
            }
        }
        __syncthreads();

        // combine + nBRC update; write h to buffer (l+1)&1
        {
            float ma = 0.0f, mc = 0.0f;
#pragma unroll
            for (int qq = 0; qq < 4; qq++) {
                const float* rq = RED + (size_t)qq * (64 * 33);
                ma += rq[b * 33 + jj]     + rq[b * 33 + 16 + jj];
                mc += rq[b * 33 + 8 + jj] + rq[b * 33 + 24 + jj];
            }
            float a  = 1.0f + tanh_acc(ia + ma);
            float cg = sigmoid_acc(ic + mc);
            float hn = cg * hreg + (1.0f - cg) * tanh_acc(io + a * hreg);
            hreg = hn;
            g_hA[(((l + 1) & 1) * 64 + b) * MEM + j] = __float2half(hn);
            g_mem[(size_t)l * (MEM * B_) + (size_t)j * B_ + b] = hn;
        }
        __syncthreads();

        // arrival: this CTA's h for step l is published
        if (t == 0) {
            __threadfence();
            atomicAdd(&g_grp[mygrp * 64], 1u);   // level l+2
        }
    }
}

// ---------------- K3: logits + softmax (4 timesteps/block) --------------------------
__global__ void __launch_bounds__(256) logits_kernel(const float* __restrict__ Wact,
                                                     const float* __restrict__ bact,
                                                     float* __restrict__ out) {
    __shared__ float Wa[MEM * DEC];
    int t = threadIdx.x;
    int l = blockIdx.x * 4 + (t >> 6);
    int b = t & 63;
    for (int idx = t; idx < MEM * DEC; idx += 256) Wa[idx] = Wact[idx];
    __syncthreads();

    float a0 = bact[0], a1 = bact[1], a2 = bact[2];
    const float* mp = g_mem + (size_t)l * MEM * B_ + b;
#pragma unroll 8
    for (int k = 0; k < MEM; k++) {
        float v = mp[(size_t)k * B_];
        a0 += v * Wa[k * 3 + 0];
        a1 += v * Wa[k * 3 + 1];
        a2 += v * Wa[k * 3 + 2];
    }
    float m  = fmaxf(a0, fmaxf(a1, a2));
    float e0 = __expf(a0 - m), e1 = __expf(a1 - m), e2 = __expf(a2 - m);
    float inv = 1.0f / (e0 + e1 + e2);
    size_t ob = ((size_t)b * L_ + l) * DEC;
    out[ob + 0] = e0 * inv;
    out[ob + 1] = e1 * inv;
    out[ob + 2] = e2 * inv;
}

// ---------------- launch --------------------------------------------------------------
typedef CUresult (*PFN_tmapEncode)(
    CUtensorMap*, CUtensorMapDataType, cuuint32_t, void*,
    const cuuint64_t*, const cuuint64_t*, const cuuint32_t*, const cuuint32_t*,
    CUtensorMapInterleave, CUtensorMapSwizzle, CUtensorMapL2promotion,
    CUtensorMapFloatOOBfill);

extern "C" void kernel_launch(void* const* d_in, const int* in_sizes, int n_in,
                              void* d_out, int out_size) {
    (void)in_sizes; (void)n_in; (void)out_size;
    const float* x   = (const float*)d_in[0];
    const float* Ws  = (const float*)d_in[1];
    const float* bs  = (const float*)d_in[2];
    const float* Wim = (const float*)d_in[3];
    const float* Wmm = (const float*)d_in[4];
    const float* Wac = (const float*)d_in[5];
    const float* bac = (const float*)d_in[6];
    float* out = (float*)d_out;

    void* hs_ptr = nullptr;
    cudaGetSymbolAddress(&hs_ptr, g_hA);
    PFN_tmapEncode enc = nullptr;
    cudaDriverEntryPointQueryResult qr;
    cudaGetDriverEntryPoint("cuTensorMapEncodeTiled", (void**)&enc,
                            cudaEnableDefault, &qr);
    CUtensorMap tmap;
    {
        cuuint64_t dims[3]    = {MEM, 128, 1};
        cuuint64_t strides[2] = {MEM * 2, (cuuint64_t)MEM * 2 * 128};
        cuuint32_t box[3]     = {64, 64, 1};
        cuuint32_t es[3]      = {1, 1, 1};
        enc(&tmap, CU_TENSOR_MAP_DATA_TYPE_FLOAT16, 3, hs_ptr,
            dims, strides, box, es,
            CU_TENSOR_MAP_INTERLEAVE_NONE, CU_TENSOR_MAP_SWIZZLE_128B,
            CU_TENSOR_MAP_L2_PROMOTION_L2_128B, CU_TENSOR_MAP_FLOAT_OOB_FILL_NONE);
    }

    cudaFuncSetAttribute(proj_tc,  cudaFuncAttributeMaxDynamicSharedMemorySize, PSM_TOT);
    cudaFuncSetAttribute(scan_tc,  cudaFuncAttributeMaxDynamicSharedMemorySize, SMEM_SCAN);

    reset_kernel<<<1, 512>>>();
    sense_kernel<<<B_ * L_ / 8, 128>>>(x, Ws, bs);
    wprep_kernel<<<24, 256>>>(Wim);
    proj_tc<<<dim3(24, 256), 128, PSM_TOT>>>();
    scan_tc<<<NCTA, NT, SMEM_SCAN>>>(Wmm, tmap);
    logits_kernel<<<L_ / 4, 256>>>(Wac, bac, out);
}